// round 11
// baseline (speedup 1.0000x reference)
#include <cuda_runtime.h>
#include <cstdint>

#define BATCH  16
#define NPTS   4096
#define NPT    1024
#define KNN    32
#define POSN   (BATCH*NPT*KNN)   // 524288 positions
#define NPAIR  (POSN/2)          // 262144 pairs
#define NTILES (POSN/64)         // 8192 tiles (32 pairs each)

// ---------------- scratch (device globals; no allocations allowed) ----------------
__device__ int    g_knn[POSN];
__device__ float  g_z[(size_t)POSN * 4];          // pair i: f4[2i]=(x0,x1,y0,y1), f4[2i+1]=(z0,z1,0,0)
__device__ float  g_y2[(size_t)POSN * 64];        // [NPAIR][64] float2 (pair-major)
__device__ float2 g_mm[(size_t)BATCH * NPT * 128];// per (b,s,c): (max_k, min_k) of pre-BN y3
__device__ double g_mom[9];                       // Sx,Sy,Sz,Sxx,Syy,Szz,Sxy,Sxz,Syz
__device__ double g_sum[3][128];
__device__ double g_sqs[3][128];
__device__ float  g_scale[3][128];
__device__ float  g_shift[3][128];

// ---- f32x2 helpers ----
__device__ __forceinline__ unsigned long long f2pack(float a, float b) {
    unsigned long long v;
    asm("mov.b64 %0, {%1, %2};" : "=l"(v) : "f"(a), "f"(b));
    return v;
}
__device__ __forceinline__ void f2unpack(unsigned long long v, float& a, float& b) {
    asm("mov.b64 {%0, %1}, %2;" : "=f"(a), "=f"(b) : "l"(v));
}
#define FMA2(d, a, b, c) \
    asm("fma.rn.f32x2 %0, %1, %2, %3;" : "=l"(d) : "l"(a), "l"(b), "l"(c))
#define ADD2(d, a, b) \
    asm("add.rn.f32x2 %0, %1, %2;" : "=l"(d) : "l"(a), "l"(b))
#define MUL2(d, a, b) \
    asm("mul.rn.f32x2 %0, %1, %2;" : "=l"(d) : "l"(a), "l"(b))

// ---------------- no-op (launch-slot alignment so ncu profiles knn) ----------------
__global__ void noop_kernel() {}

// ---------------- zero stats ----------------
__global__ void zero_stats_kernel() {
    int t = threadIdx.x;           // 512 threads
    if (t < 128)      { g_sum[1][t] = 0.0;       g_sqs[1][t] = 0.0; }
    else if (t < 256) { g_sum[2][t - 128] = 0.0; g_sqs[2][t - 128] = 0.0; }
    if (t < 9) g_mom[t] = 0.0;
}

// ---------------- farthest point sampling ----------------
// One block per batch, 512 threads, 8 points/thread (4 f32x2 pairs) in regs.
// Fewer warps -> less per-warp fixed reduce overhead per iteration (issue-
// bound regime per R10 profile). Warp stage: REDUX.MAX(dist bits) + tie
// REDUX.MIN(index). Cross-warp: 16 partials padded to 32 with sentinels,
// same REDUX pair, one barrier/iter. Exact jnp semantics (max dist, min idx).
__global__ void fps_kernel(const float* __restrict__ xyz,
                           const int* __restrict__ initf,
                           float* __restrict__ newxyz) {
    __shared__ unsigned wkd[2][32], wki[2][32];

    const int b = blockIdx.x, tid = threadIdx.x;
    const int lane = tid & 31, w = tid >> 5;     // w < 16
    const float* xb = xyz + (size_t)b * NPTS * 3;

    unsigned long long px2[4], py2[4], pz2[4];
    float dist[8];
#pragma unroll
    for (int u = 0; u < 4; u++) {
        int p0 = tid + 512 * (2 * u);
        int p1 = tid + 512 * (2 * u + 1);
        px2[u] = f2pack(xb[3 * p0 + 0], xb[3 * p1 + 0]);
        py2[u] = f2pack(xb[3 * p0 + 1], xb[3 * p1 + 1]);
        pz2[u] = f2pack(xb[3 * p0 + 2], xb[3 * p1 + 2]);
        dist[2 * u] = 1e10f; dist[2 * u + 1] = 1e10f;
    }
    if (tid < 32 && lane >= 16) {                 // sentinel partials (never win)
        wkd[0][lane] = 0u; wki[0][lane] = 0xFFFFFFFFu;
        wkd[1][lane] = 0u; wki[1][lane] = 0xFFFFFFFFu;
    }
    int f = initf[b];
    __syncthreads();

    for (int it = 0; it < NPT; it++) {
        float cx = xb[3 * f + 0], cy = xb[3 * f + 1], cz = xb[3 * f + 2];
        if (tid == 0) {
            float* o = newxyz + (size_t)(b * NPT + it) * 3;
            o[0] = cx; o[1] = cy; o[2] = cz;
        }
        unsigned long long ncx = f2pack(-cx, -cx);
        unsigned long long ncy = f2pack(-cy, -cy);
        unsigned long long ncz = f2pack(-cz, -cz);

#pragma unroll
        for (int u = 0; u < 4; u++) {
            unsigned long long dx, dy, dz, xx, yy, zz, ss, dd;
            ADD2(dx, px2[u], ncx);
            ADD2(dy, py2[u], ncy);
            ADD2(dz, pz2[u], ncz);
            MUL2(xx, dx, dx);
            MUL2(yy, dy, dy);
            MUL2(zz, dz, dz);
            ADD2(ss, xx, yy);
            ADD2(dd, ss, zz);
            float d0, d1;
            f2unpack(dd, d0, d1);
            dist[2 * u]     = fminf(dist[2 * u], d0);
            dist[2 * u + 1] = fminf(dist[2 * u + 1], d1);
        }
        // per-thread value max (depth 3)
        float a0 = fmaxf(dist[0], dist[4]);
        float a1 = fmaxf(dist[1], dist[5]);
        float a2 = fmaxf(dist[2], dist[6]);
        float a3 = fmaxf(dist[3], dist[7]);
        float dmax = fmaxf(fmaxf(a0, a1), fmaxf(a2, a3));

        // warp max dist (u32 order valid: all dists nonneg)
        unsigned mw = __reduce_max_sync(0xFFFFFFFFu, __float_as_uint(dmax));

        // min index among this thread's slots hitting mw
        unsigned ic[8];
#pragma unroll
        for (int j = 0; j < 8; j++)
            ic[j] = (__float_as_uint(dist[j]) == mw)
                      ? (unsigned)(tid + 512 * j) : 0xFFFFFFFFu;
#pragma unroll
        for (int o = 4; o; o >>= 1)
#pragma unroll
            for (int i = 0; i < 4; i++)
                if (i < o) ic[i] = umin(ic[i], ic[i + o]);
        unsigned widx = __reduce_min_sync(0xFFFFFFFFu, ic[0]);

        if (lane == 0) { wkd[it & 1][w] = mw; wki[it & 1][w] = widx; }
        __syncthreads();

        // cross-warp: lane l holds partial of warp l (16 real + 16 sentinel)
        unsigned dl = wkd[it & 1][lane];
        unsigned il = wki[it & 1][lane];
        unsigned dm = __reduce_max_sync(0xFFFFFFFFu, dl);
        unsigned cand = (dl == dm) ? il : 0xFFFFFFFFu;
        f = (int)__reduce_min_sync(0xFFFFFFFFu, cand);
    }
}

// ---------------- kNN (top-33 smallest, drop rank 0) ----------------
// Warp per query; register bitonic-32 sort, then 33-step merge using
// REDUX min on dist bits + tie REDUX min on index (exact stable order).
// (cur,next) kept in registers: the dependent sl[tid][h] LDS sits one
// advance behind the critical chain.
__global__ void knn_kernel(const float* __restrict__ newxyz) {
    __shared__ unsigned long long sl[128][33];   // padded: conflict-free
    float* qx = (float*)&sl[0][0];               // coords aliased (dead after r[] built)
    float* qy = qx + NPT;
    float* qz = qy + NPT;

    const int tid = threadIdx.x, lane = tid & 31, w = tid >> 5;
    const int b = blockIdx.x >> 8;
    const int s = ((blockIdx.x & 255) << 2) | w;
    const float* nb = newxyz + (size_t)b * NPT * 3;

    for (int i = tid; i < NPT; i += 128) {
        qx[i] = nb[3 * i + 0];
        qy[i] = nb[3 * i + 1];
        qz[i] = nb[3 * i + 2];
    }
    __syncthreads();

    const float x = qx[s], y = qy[s], z = qz[s];

    unsigned long long r[32];
#pragma unroll
    for (int u = 0; u < 32; u++) {
        int j = lane + 32 * u;
        float dx = __fsub_rn(qx[j], x);
        float dy = __fsub_rn(qy[j], y);
        float dz = __fsub_rn(qz[j], z);
        float d = __fadd_rn(__fadd_rn(__fmul_rn(dx, dx), __fmul_rn(dy, dy)),
                            __fmul_rn(dz, dz));
        r[u] = ((unsigned long long)__float_as_uint(d) << 32) | (unsigned)j;
    }
    __syncthreads();   // coords consumed; sl may be overwritten

#pragma unroll
    for (int k = 2; k <= 32; k <<= 1) {
#pragma unroll
        for (int j = k >> 1; j > 0; j >>= 1) {
#pragma unroll
            for (int i = 0; i < 32; i++) {
                int ixj = i ^ j;
                if (ixj > i) {
                    bool up = ((i & k) == 0);
                    unsigned long long a = r[i], bb = r[ixj];
                    if ((a > bb) == up) { r[i] = bb; r[ixj] = a; }
                }
            }
        }
    }

#pragma unroll
    for (int u = 2; u < 32; u++) sl[tid][u] = r[u];   // ranks 0,1 stay in regs

    unsigned ch = (unsigned)(r[0] >> 32), cl = (unsigned)r[0];   // current
    unsigned nh = (unsigned)(r[1] >> 32), nl = (unsigned)r[1];   // prefetched next
    int h = 2;
    int myidx = 0;
    for (int t = 0; t < 33; t++) {
        unsigned dm = __reduce_min_sync(0xFFFFFFFFu, ch);
        unsigned jc = (ch == dm) ? cl : 0xFFFFFFFFu;
        unsigned jm = __reduce_min_sync(0xFFFFFFFFu, jc);
        if (t && lane == t - 1) myidx = (int)jm;
        if (ch == dm && cl == jm) {          // unique winner advances
            ch = nh; cl = nl;
            if (h < 32) {
                unsigned long long nx = sl[tid][h];
                nh = (unsigned)(nx >> 32);
                nl = (unsigned)nx;
            } else {
                nh = 0xFFFFFFFFu;            // sentinel (never a real dist)
                nl = 0xFFFFFFFFu;
            }
            h++;
        }
    }
    g_knn[(size_t)(b * NPT + s) * KNN + lane] = myidx;
}

// ---------------- grouping: gather z = xyz[knn] - center, 9 moments ----------------
__global__ void group_kernel(const float* __restrict__ xyz,
                             const float* __restrict__ newxyz) {
    __shared__ float wm[8][9];
    const int i = blockIdx.x * 256 + threadIdx.x;   // pair id < NPAIR
    int2 jj = ((const int2*)g_knn)[i];
    int bs = i >> 4;
    int b = bs >> 10;
    const float* np = newxyz + (size_t)bs * 3;
    float nx = np[0], ny = np[1], nz = np[2];
    const float* p0 = xyz + (size_t)(b * NPTS + jj.x) * 3;
    const float* p1 = xyz + (size_t)(b * NPTS + jj.y) * 3;
    float x0 = p0[0] - nx, y0 = p0[1] - ny, z0 = p0[2] - nz;
    float x1 = p1[0] - nx, y1 = p1[1] - ny, z1 = p1[2] - nz;
    float4* z4 = (float4*)g_z;
    z4[2 * i]     = make_float4(x0, x1, y0, y1);
    z4[2 * i + 1] = make_float4(z0, z1, 0.f, 0.f);

    float m[9] = { x0 + x1, y0 + y1, z0 + z1,
                   x0 * x0 + x1 * x1, y0 * y0 + y1 * y1, z0 * z0 + z1 * z1,
                   x0 * y0 + x1 * y1, x0 * z0 + x1 * z1, y0 * z0 + y1 * z1 };
#pragma unroll
    for (int u = 0; u < 9; u++) {
        float v = m[u];
#pragma unroll
        for (int o = 16; o; o >>= 1) v += __shfl_xor_sync(0xFFFFFFFFu, v, o);
        if ((threadIdx.x & 31) == 0) wm[threadIdx.x >> 5][u] = v;
    }
    __syncthreads();
    if (threadIdx.x < 9) {
        float s = 0.f;
#pragma unroll
        for (int ww = 0; ww < 8; ww++) s += wm[ww][threadIdx.x];
        atomicAdd(&g_mom[threadIdx.x], (double)s);
    }
}

// ---------------- BN1 stats from moments ----------------
__global__ void finalize1_kernel(const float* __restrict__ W1,
                                 const float* __restrict__ b1,
                                 const float* __restrict__ g1,
                                 const float* __restrict__ be1) {
    int c = threadIdx.x;   // 64
    double w0 = W1[3 * c], w1 = W1[3 * c + 1], w2 = W1[3 * c + 2], b = b1[c];
    double Sx = g_mom[0], Sy = g_mom[1], Sz = g_mom[2];
    double Sxx = g_mom[3], Syy = g_mom[4], Szz = g_mom[5];
    double Sxy = g_mom[6], Sxz = g_mom[7], Syz = g_mom[8];
    double N = (double)POSN;
    double ws = w0 * Sx + w1 * Sy + w2 * Sz;
    double mean = (ws + N * b) / N;
    double ey2 = (w0 * w0 * Sxx + w1 * w1 * Syy + w2 * w2 * Szz
                + 2.0 * (w0 * w1 * Sxy + w0 * w2 * Sxz + w1 * w2 * Syz)
                + 2.0 * b * ws + N * b * b) / N;
    double var = ey2 - mean * mean;
    if (var < 0.0) var = 0.0;
    float sc = g1[c] * rsqrtf((float)var + 1e-5f);
    g_scale[0][c] = sc;
    g_shift[0][c] = be1[c] - (float)mean * sc;
}

// ---------------- layer 2: recompute y1 from z + BN1 + ReLU, 64->64 GEMM ----------------
// Weights in shared as pre-packed (w,w) f32x2 -> ~64 fewer regs -> 3 blocks/SM.
__global__ void __launch_bounds__(256, 3)
layer2_kernel(const float* __restrict__ W, const float* __restrict__ bias,
              const float* __restrict__ W1, const float* __restrict__ b1) {
    __shared__ unsigned long long wsp[64][64];  // 32KB: [ci][c] = (W[c][ci], W[c][ci])
    __shared__ float4 zsh[64];                  // tile's z (32 pairs x 2 float4)
    __shared__ float2 tile2[32][66];            // [pair][ci], padded
    __shared__ float4 sw1[64];                  // (w0,w1,w2,b) per layer1 channel
    __shared__ float4 bnp[32];                  // (sc0,sh0,sc1,sh1) per channel pair
    __shared__ float red[256], red2[256];

    const int tid = threadIdx.x;
    const int c = tid & 63, q = tid >> 6;       // q<4, 8 pairs/thread
    if (tid < 64) sw1[tid] = make_float4(W1[3 * tid], W1[3 * tid + 1],
                                         W1[3 * tid + 2], b1[tid]);
    if (tid < 32) bnp[tid] = make_float4(g_scale[0][2 * tid], g_shift[0][2 * tid],
                                         g_scale[0][2 * tid + 1], g_shift[0][2 * tid + 1]);
#pragma unroll
    for (int e = tid; e < 4096; e += 256) {
        int ci = e >> 6, cc = e & 63;
        float wv = W[cc * 64 + ci];
        wsp[ci][cc] = f2pack(wv, wv);
    }
    const unsigned long long bb2 = f2pack(bias[c], bias[c]);
    float s = 0.f, s2 = 0.f;
    __syncthreads();

    const float4* z4 = (const float4*)g_z;
    float2* yout = (float2*)g_y2;

    for (int tile = blockIdx.x; tile < NTILES; tile += gridDim.x) {
        if (tid < 64) zsh[tid] = z4[(size_t)tile * 64 + tid];
        __syncthreads();
#pragma unroll
        for (int rr = 0; rr < 4; rr++) {
            int e = tid + 256 * rr;
            int pair = e >> 5, ciq = e & 31;
            float4 xy = zsh[2 * pair];          // x0,x1,y0,y1
            float4 zz = zsh[2 * pair + 1];      // z0,z1,-,-
            float4 wv0 = sw1[2 * ciq], wv1 = sw1[2 * ciq + 1];
            float4 bn = bnp[ciq];
            float y00 = fmaf(wv0.x, xy.x, fmaf(wv0.y, xy.z, fmaf(wv0.z, zz.x, wv0.w)));
            float y01 = fmaf(wv0.x, xy.y, fmaf(wv0.y, xy.w, fmaf(wv0.z, zz.y, wv0.w)));
            float y10 = fmaf(wv1.x, xy.x, fmaf(wv1.y, xy.z, fmaf(wv1.z, zz.x, wv1.w)));
            float y11 = fmaf(wv1.x, xy.y, fmaf(wv1.y, xy.w, fmaf(wv1.z, zz.y, wv1.w)));
            float4 a;
            a.x = fmaxf(fmaf(y00, bn.x, bn.y), 0.f);
            a.y = fmaxf(fmaf(y01, bn.x, bn.y), 0.f);
            a.z = fmaxf(fmaf(y10, bn.z, bn.w), 0.f);
            a.w = fmaxf(fmaf(y11, bn.z, bn.w), 0.f);
            *(float4*)&tile2[pair][2 * ciq] = a;
        }
        __syncthreads();

        unsigned long long acc2[8];
#pragma unroll
        for (int m = 0; m < 8; m++) acc2[m] = bb2;
#pragma unroll
        for (int cq = 0; cq < 32; cq++) {
            unsigned long long wA = wsp[2 * cq][c];
            unsigned long long wB = wsp[2 * cq + 1][c];
#pragma unroll
            for (int m = 0; m < 8; m++) {
                ulonglong2 zv = *(const ulonglong2*)&tile2[q * 8 + m][2 * cq];
                FMA2(acc2[m], wA, zv.x, acc2[m]);
                FMA2(acc2[m], wB, zv.y, acc2[m]);
            }
        }

        float2* yo = yout + ((size_t)tile * 32 + q * 8) * 64 + c;
#pragma unroll
        for (int m = 0; m < 8; m++) {
            float a0, a1;
            f2unpack(acc2[m], a0, a1);
            yo[(size_t)m * 64] = make_float2(a0, a1);
            s += a0 + a1;
            s2 += a0 * a0 + a1 * a1;
        }
        __syncthreads();
    }

    red[tid] = s; red2[tid] = s2;
    __syncthreads();
    if (tid < 128) { red[tid] += red[tid + 128]; red2[tid] += red2[tid + 128]; }
    __syncthreads();
    if (tid < 64) {
        atomicAdd(&g_sum[1][tid], (double)(red[tid] + red[tid + 64]));
        atomicAdd(&g_sqs[1][tid], (double)(red2[tid] + red2[tid + 64]));
    }
}

// ---------------- layer 3: BN2+ReLU on load, 64->128 GEMM, fused k-min/max ----------------
// Weights in shared (64KB) -> low regs -> 2 blocks/SM (smem-limited).
__global__ void __launch_bounds__(256, 2)
layer3_kernel(const float* __restrict__ W, const float* __restrict__ bias) {
    __shared__ unsigned long long wsp[64][128]; // 64KB: [ci][c] = (W[c][ci], W[c][ci])
    __shared__ float2 tile2[32][66];
    __shared__ float4 bnp[32];
    __shared__ float red[256], red2[256];

    const int tid = threadIdx.x;
    const int c = tid & 127, q = tid >> 7;      // q<2, 16 pairs (= one s-group) / thread
    if (tid < 32) bnp[tid] = make_float4(g_scale[1][2 * tid], g_shift[1][2 * tid],
                                         g_scale[1][2 * tid + 1], g_shift[1][2 * tid + 1]);
#pragma unroll
    for (int e = tid; e < 8192; e += 256) {
        int ci = e >> 7, cc = e & 127;
        float wv = W[cc * 64 + ci];
        wsp[ci][cc] = f2pack(wv, wv);
    }
    const unsigned long long bb2 = f2pack(bias[c], bias[c]);
    float s = 0.f, s2 = 0.f;
    __syncthreads();

    const float2* yin = (const float2*)g_y2;

    for (int tile = blockIdx.x; tile < NTILES; tile += gridDim.x) {
#pragma unroll
        for (int rr = 0; rr < 4; rr++) {
            int e = tid + 256 * rr;
            int pair = e >> 5, ciq = e & 31;
            float4 v = *(const float4*)(yin + ((size_t)tile * 32 + pair) * 64 + 2 * ciq);
            float4 bn = bnp[ciq];
            v.x = fmaxf(fmaf(v.x, bn.x, bn.y), 0.f);
            v.y = fmaxf(fmaf(v.y, bn.x, bn.y), 0.f);
            v.z = fmaxf(fmaf(v.z, bn.z, bn.w), 0.f);
            v.w = fmaxf(fmaf(v.w, bn.z, bn.w), 0.f);
            *(float4*)&tile2[pair][2 * ciq] = v;
        }
        __syncthreads();

        unsigned long long acc2[16];
#pragma unroll
        for (int m = 0; m < 16; m++) acc2[m] = bb2;
#pragma unroll
        for (int cq = 0; cq < 32; cq++) {
            unsigned long long wA = wsp[2 * cq][c];
            unsigned long long wB = wsp[2 * cq + 1][c];
#pragma unroll
            for (int m = 0; m < 16; m++) {
                ulonglong2 zv = *(const ulonglong2*)&tile2[q * 16 + m][2 * cq];
                FMA2(acc2[m], wA, zv.x, acc2[m]);
                FMA2(acc2[m], wB, zv.y, acc2[m]);
            }
        }

        float mx = -3.402823466e38f, mn = 3.402823466e38f;
#pragma unroll
        for (int m = 0; m < 16; m++) {
            float a0, a1;
            f2unpack(acc2[m], a0, a1);
            s += a0 + a1;
            s2 += a0 * a0 + a1 * a1;
            mx = fmaxf(mx, fmaxf(a0, a1));
            mn = fminf(mn, fminf(a0, a1));
        }
        g_mm[((size_t)tile * 2 + q) * 128 + c] = make_float2(mx, mn);
        __syncthreads();
    }

    red[tid] = s; red2[tid] = s2;
    __syncthreads();
    if (tid < 128) {
        atomicAdd(&g_sum[2][tid], (double)(red[tid] + red[tid + 128]));
        atomicAdd(&g_sqs[2][tid], (double)(red2[tid] + red2[tid + 128]));
    }
}

// ---------------- BN finalize (layers 2,3) ----------------
__global__ void finalize_kernel(int l, const float* __restrict__ g,
                                const float* __restrict__ be, int C) {
    int c = threadIdx.x;
    if (c < C) {
        double n = (double)POSN;
        double m = g_sum[l][c] / n;
        double v = g_sqs[l][c] / n - m * m;
        if (v < 0.0) v = 0.0;
        float sc = g[c] * rsqrtf((float)v + 1e-5f);
        g_scale[l][c] = sc;
        g_shift[l][c] = be[c] - (float)m * sc;
    }
}

// ---------------- final: BN3+ReLU applied to max/min, transpose to [b,c,s] ----------------
__global__ void final_kernel(float* __restrict__ out) {
    __shared__ float t[128 * 33];
    __shared__ float ssc[128], ssh[128];
    const int blk = blockIdx.x;
    const int b = blk >> 5, st = blk & 31;
    const int tid = threadIdx.x;
    if (tid < 128) { ssc[tid] = g_scale[2][tid]; ssh[tid] = g_shift[2][tid]; }
    __syncthreads();
#pragma unroll
    for (int rr = 0; rr < 16; rr++) {
        int e = tid + 256 * rr;                 // 4096 = 32 s x 128 c
        int sl = e >> 7, cc = e & 127;
        float2 v = g_mm[((size_t)(b * NPT + st * 32 + sl)) * 128 + cc];
        float sc = ssc[cc], sh = ssh[cc];
        float val = (sc >= 0.f) ? fmaf(v.x, sc, sh) : fmaf(v.y, sc, sh);
        t[cc * 33 + sl] = fmaxf(val, 0.f);
    }
    __syncthreads();
#pragma unroll
    for (int rr = 0; rr < 16; rr++) {
        int e = tid + 256 * rr;
        int c2 = e >> 5, s2 = e & 31;
        out[(size_t)(b * 128 + c2) * NPT + st * 32 + s2] = t[c2 * 33 + s2];
    }
}

// ---------------- launch ----------------
extern "C" void kernel_launch(void* const* d_in, const int* in_sizes, int n_in,
                              void* d_out, int out_size) {
    const float* xyz   = (const float*)d_in[0];
    const int*   initf = (const int*)d_in[1];
    const float* W1 = (const float*)d_in[2];
    const float* b1 = (const float*)d_in[3];
    const float* g1 = (const float*)d_in[4];
    const float* be1 = (const float*)d_in[5];
    const float* W2 = (const float*)d_in[6];
    const float* b2 = (const float*)d_in[7];
    const float* g2 = (const float*)d_in[8];
    const float* be2 = (const float*)d_in[9];
    const float* W3 = (const float*)d_in[10];
    const float* b3 = (const float*)d_in[11];
    const float* g3 = (const float*)d_in[12];
    const float* be3 = (const float*)d_in[13];

    float* out = (float*)d_out;
    float* newxyz = out;                               // [16,1024,3]
    float* newpts = out + (size_t)BATCH * NPT * 3;     // [16,128,1024]

    fps_kernel<<<BATCH, 512>>>(xyz, initf, newxyz);    // slot 1
    zero_stats_kernel<<<1, 512>>>();                   // slot 2
    noop_kernel<<<1, 32>>>();                          // slot 3
    knn_kernel<<<BATCH * 256, 128>>>(newxyz);          // slot 4 -> profiled
    group_kernel<<<NPAIR / 256, 256>>>(xyz, newxyz);
    finalize1_kernel<<<1, 64>>>(W1, b1, g1, be1);
    layer2_kernel<<<1184, 256>>>(W2, b2, W1, b1);
    finalize_kernel<<<1, 128>>>(1, g2, be2, 64);
    layer3_kernel<<<1184, 256>>>(W3, b3);
    finalize_kernel<<<1, 128>>>(2, g3, be3, 128);
    final_kernel<<<512, 256>>>(newpts);
}

// round 13
// speedup vs baseline: 1.2971x; 1.2971x over previous
#include <cuda_runtime.h>
#include <cuda_bf16.h>
#include <cstdint>

#define BATCH  16
#define NPTS   4096
#define NPT    1024
#define KNN    32
#define POSN   (BATCH*NPT*KNN)   // 524288 positions
#define NPAIR  (POSN/2)          // 262144 pairs
#define NTILES (POSN/64)         // 8192 tiles (32 pairs) for layer2
#define L3T    (BATCH*NPT)       // 16384 layer3 tiles (one s-group = 32 positions)

// ---------------- scratch (device globals; no allocations allowed) ----------------
__device__ int    g_knn[POSN];
__device__ float  g_z[(size_t)POSN * 4];
__device__ float  g_y2[(size_t)POSN * 64];        // [NPAIR][64] float2 (pair-major)
__device__ float2 g_mm[(size_t)BATCH * NPT * 128];// per (b,s,c): (max_k, min_k) of pre-BN y3
__device__ double g_mom[9];
__device__ double g_sum[3][128];
__device__ double g_sqs[3][128];
__device__ float  g_scale[3][128];
__device__ float  g_shift[3][128];

// ---- f32x2 helpers ----
__device__ __forceinline__ unsigned long long f2pack(float a, float b) {
    unsigned long long v;
    asm("mov.b64 %0, {%1, %2};" : "=l"(v) : "f"(a), "f"(b));
    return v;
}
__device__ __forceinline__ void f2unpack(unsigned long long v, float& a, float& b) {
    asm("mov.b64 {%0, %1}, %2;" : "=f"(a), "=f"(b) : "l"(v));
}
#define FMA2(d, a, b, c) \
    asm("fma.rn.f32x2 %0, %1, %2, %3;" : "=l"(d) : "l"(a), "l"(b), "l"(c))
#define ADD2(d, a, b) \
    asm("add.rn.f32x2 %0, %1, %2;" : "=l"(d) : "l"(a), "l"(b))
#define MUL2(d, a, b) \
    asm("mul.rn.f32x2 %0, %1, %2;" : "=l"(d) : "l"(a), "l"(b))

__device__ __forceinline__ uint32_t smem_u32(const void* p) {
    uint32_t a;
    asm("{ .reg .u64 t; cvta.to.shared.u64 t, %1; cvt.u32.u64 %0, t; }"
        : "=r"(a) : "l"(p));
    return a;
}

// bf16 hi/lo split: returns packed (hi(a),hi(b)); lo_pack = (lo(a),lo(b))
__device__ __forceinline__ unsigned bfsplit_pack(float a, float b, unsigned& lo_pack) {
    __nv_bfloat16 ha = __float2bfloat16(a), hb = __float2bfloat16(b);
    __nv_bfloat16 la = __float2bfloat16(a - __bfloat162float(ha));
    __nv_bfloat16 lb = __float2bfloat16(b - __bfloat162float(hb));
    lo_pack = (unsigned)__bfloat16_as_ushort(la) |
              ((unsigned)__bfloat16_as_ushort(lb) << 16);
    return (unsigned)__bfloat16_as_ushort(ha) |
           ((unsigned)__bfloat16_as_ushort(hb) << 16);
}

// m16n8k16 bf16 mma, fp32 accumulate (baseline PTX, sm_80+)
__device__ __forceinline__ void mma16816(float d[4], const unsigned a[4],
                                         unsigned b0, unsigned b1) {
    asm volatile(
        "mma.sync.aligned.m16n8k16.row.col.f32.bf16.bf16.f32 "
        "{%0,%1,%2,%3}, {%4,%5,%6,%7}, {%8,%9}, {%0,%1,%2,%3};"
        : "+f"(d[0]), "+f"(d[1]), "+f"(d[2]), "+f"(d[3])
        : "r"(a[0]), "r"(a[1]), "r"(a[2]), "r"(a[3]), "r"(b0), "r"(b1));
}

// ---------------- no-op (launch-slot alignment) ----------------
__global__ void noop_kernel() {}

// ---------------- zero stats ----------------
__global__ void zero_stats_kernel() {
    int t = threadIdx.x;           // 512 threads
    if (t < 128)      { g_sum[1][t] = 0.0;       g_sqs[1][t] = 0.0; }
    else if (t < 256) { g_sum[2][t - 128] = 0.0; g_sqs[2][t - 128] = 0.0; }
    if (t < 9) g_mom[t] = 0.0;
}

// ---------------- farthest point sampling (1024 thr, 4 pts/thread; R10) ----------------
__global__ void fps_kernel(const float* __restrict__ xyz,
                           const int* __restrict__ initf,
                           float* __restrict__ newxyz) {
    __shared__ unsigned wkd[2][32], wki[2][32];

    const int b = blockIdx.x, tid = threadIdx.x;
    const int lane = tid & 31, w = tid >> 5;
    const float* xb = xyz + (size_t)b * NPTS * 3;

    unsigned long long px2[2], py2[2], pz2[2];
    float dist[4];
#pragma unroll
    for (int u = 0; u < 2; u++) {
        int p0 = tid + 1024 * (2 * u);
        int p1 = tid + 1024 * (2 * u + 1);
        px2[u] = f2pack(xb[3 * p0 + 0], xb[3 * p1 + 0]);
        py2[u] = f2pack(xb[3 * p0 + 1], xb[3 * p1 + 1]);
        pz2[u] = f2pack(xb[3 * p0 + 2], xb[3 * p1 + 2]);
        dist[2 * u] = 1e10f; dist[2 * u + 1] = 1e10f;
    }
    int f = initf[b];
    __syncthreads();

    for (int it = 0; it < NPT; it++) {
        float cx = xb[3 * f + 0], cy = xb[3 * f + 1], cz = xb[3 * f + 2];
        if (tid == 0) {
            float* o = newxyz + (size_t)(b * NPT + it) * 3;
            o[0] = cx; o[1] = cy; o[2] = cz;
        }
        unsigned long long ncx = f2pack(-cx, -cx);
        unsigned long long ncy = f2pack(-cy, -cy);
        unsigned long long ncz = f2pack(-cz, -cz);

#pragma unroll
        for (int u = 0; u < 2; u++) {
            unsigned long long dx, dy, dz, xx, yy, zz, ss, dd;
            ADD2(dx, px2[u], ncx);
            ADD2(dy, py2[u], ncy);
            ADD2(dz, pz2[u], ncz);
            MUL2(xx, dx, dx);
            MUL2(yy, dy, dy);
            MUL2(zz, dz, dz);
            ADD2(ss, xx, yy);
            ADD2(dd, ss, zz);
            float d0, d1;
            f2unpack(dd, d0, d1);
            dist[2 * u]     = fminf(dist[2 * u], d0);
            dist[2 * u + 1] = fminf(dist[2 * u + 1], d1);
        }
        float dmax = fmaxf(fmaxf(dist[0], dist[1]), fmaxf(dist[2], dist[3]));
        unsigned mw = __reduce_max_sync(0xFFFFFFFFu, __float_as_uint(dmax));
        unsigned ic[4];
#pragma unroll
        for (int j = 0; j < 4; j++)
            ic[j] = (__float_as_uint(dist[j]) == mw)
                      ? (unsigned)(tid + 1024 * j) : 0xFFFFFFFFu;
        unsigned widx = __reduce_min_sync(0xFFFFFFFFu,
                          umin(umin(ic[0], ic[1]), umin(ic[2], ic[3])));

        if (lane == 0) { wkd[it & 1][w] = mw; wki[it & 1][w] = widx; }
        __syncthreads();
        unsigned dl = wkd[it & 1][lane];
        unsigned il = wki[it & 1][lane];
        unsigned dm = __reduce_max_sync(0xFFFFFFFFu, dl);
        unsigned cand = (dl == dm) ? il : 0xFFFFFFFFu;
        f = (int)__reduce_min_sync(0xFFFFFFFFu, cand);
    }
}

// ---------------- kNN (top-33 smallest, drop rank 0) ----------------
__global__ void knn_kernel(const float* __restrict__ newxyz) {
    __shared__ unsigned long long sl[128][33];
    float* qx = (float*)&sl[0][0];
    float* qy = qx + NPT;
    float* qz = qy + NPT;

    const int tid = threadIdx.x, lane = tid & 31, w = tid >> 5;
    const int b = blockIdx.x >> 8;
    const int s = ((blockIdx.x & 255) << 2) | w;
    const float* nb = newxyz + (size_t)b * NPT * 3;

    for (int i = tid; i < NPT; i += 128) {
        qx[i] = nb[3 * i + 0];
        qy[i] = nb[3 * i + 1];
        qz[i] = nb[3 * i + 2];
    }
    __syncthreads();

    const float x = qx[s], y = qy[s], z = qz[s];

    unsigned long long r[32];
#pragma unroll
    for (int u = 0; u < 32; u++) {
        int j = lane + 32 * u;
        float dx = __fsub_rn(qx[j], x);
        float dy = __fsub_rn(qy[j], y);
        float dz = __fsub_rn(qz[j], z);
        float d = __fadd_rn(__fadd_rn(__fmul_rn(dx, dx), __fmul_rn(dy, dy)),
                            __fmul_rn(dz, dz));
        r[u] = ((unsigned long long)__float_as_uint(d) << 32) | (unsigned)j;
    }
    __syncthreads();

#pragma unroll
    for (int k = 2; k <= 32; k <<= 1) {
#pragma unroll
        for (int j = k >> 1; j > 0; j >>= 1) {
#pragma unroll
            for (int i = 0; i < 32; i++) {
                int ixj = i ^ j;
                if (ixj > i) {
                    bool up = ((i & k) == 0);
                    unsigned long long a = r[i], bb = r[ixj];
                    if ((a > bb) == up) { r[i] = bb; r[ixj] = a; }
                }
            }
        }
    }

#pragma unroll
    for (int u = 2; u < 32; u++) sl[tid][u] = r[u];

    unsigned ch = (unsigned)(r[0] >> 32), cl = (unsigned)r[0];
    unsigned nh = (unsigned)(r[1] >> 32), nl = (unsigned)r[1];
    int h = 2;
    int myidx = 0;
    for (int t = 0; t < 33; t++) {
        unsigned dm = __reduce_min_sync(0xFFFFFFFFu, ch);
        unsigned jc = (ch == dm) ? cl : 0xFFFFFFFFu;
        unsigned jm = __reduce_min_sync(0xFFFFFFFFu, jc);
        if (t && lane == t - 1) myidx = (int)jm;
        if (ch == dm && cl == jm) {
            ch = nh; cl = nl;
            if (h < 32) {
                unsigned long long nx = sl[tid][h];
                nh = (unsigned)(nx >> 32);
                nl = (unsigned)nx;
            } else {
                nh = 0xFFFFFFFFu;
                nl = 0xFFFFFFFFu;
            }
            h++;
        }
    }
    g_knn[(size_t)(b * NPT + s) * KNN + lane] = myidx;
}

// ---------------- grouping: gather z = xyz[knn] - center, 9 moments ----------------
__global__ void group_kernel(const float* __restrict__ xyz,
                             const float* __restrict__ newxyz) {
    __shared__ float wm[8][9];
    const int i = blockIdx.x * 256 + threadIdx.x;
    int2 jj = ((const int2*)g_knn)[i];
    int bs = i >> 4;
    int b = bs >> 10;
    const float* np = newxyz + (size_t)bs * 3;
    float nx = np[0], ny = np[1], nz = np[2];
    const float* p0 = xyz + (size_t)(b * NPTS + jj.x) * 3;
    const float* p1 = xyz + (size_t)(b * NPTS + jj.y) * 3;
    float x0 = p0[0] - nx, y0 = p0[1] - ny, z0 = p0[2] - nz;
    float x1 = p1[0] - nx, y1 = p1[1] - ny, z1 = p1[2] - nz;
    float4* z4 = (float4*)g_z;
    z4[2 * i]     = make_float4(x0, x1, y0, y1);
    z4[2 * i + 1] = make_float4(z0, z1, 0.f, 0.f);

    float m[9] = { x0 + x1, y0 + y1, z0 + z1,
                   x0 * x0 + x1 * x1, y0 * y0 + y1 * y1, z0 * z0 + z1 * z1,
                   x0 * y0 + x1 * y1, x0 * z0 + x1 * z1, y0 * z0 + y1 * z1 };
#pragma unroll
    for (int u = 0; u < 9; u++) {
        float v = m[u];
#pragma unroll
        for (int o = 16; o; o >>= 1) v += __shfl_xor_sync(0xFFFFFFFFu, v, o);
        if ((threadIdx.x & 31) == 0) wm[threadIdx.x >> 5][u] = v;
    }
    __syncthreads();
    if (threadIdx.x < 9) {
        float s = 0.f;
#pragma unroll
        for (int ww = 0; ww < 8; ww++) s += wm[ww][threadIdx.x];
        atomicAdd(&g_mom[threadIdx.x], (double)s);
    }
}

// ---------------- BN1 stats from moments ----------------
__global__ void finalize1_kernel(const float* __restrict__ W1,
                                 const float* __restrict__ b1,
                                 const float* __restrict__ g1,
                                 const float* __restrict__ be1) {
    int c = threadIdx.x;   // 64
    double w0 = W1[3 * c], w1 = W1[3 * c + 1], w2 = W1[3 * c + 2], b = b1[c];
    double Sx = g_mom[0], Sy = g_mom[1], Sz = g_mom[2];
    double Sxx = g_mom[3], Syy = g_mom[4], Szz = g_mom[5];
    double Sxy = g_mom[6], Sxz = g_mom[7], Syz = g_mom[8];
    double N = (double)POSN;
    double ws = w0 * Sx + w1 * Sy + w2 * Sz;
    double mean = (ws + N * b) / N;
    double ey2 = (w0 * w0 * Sxx + w1 * w1 * Syy + w2 * w2 * Szz
                + 2.0 * (w0 * w1 * Sxy + w0 * w2 * Sxz + w1 * w2 * Syz)
                + 2.0 * b * ws + N * b * b) / N;
    double var = ey2 - mean * mean;
    if (var < 0.0) var = 0.0;
    float sc = g1[c] * rsqrtf((float)var + 1e-5f);
    g_scale[0][c] = sc;
    g_shift[0][c] = be1[c] - (float)mean * sc;
}

// ---------------- layer 2: recompute y1 from z + BN1 + ReLU, 64->64 GEMM (FFMA2) -------
__global__ void __launch_bounds__(256, 3)
layer2_kernel(const float* __restrict__ W, const float* __restrict__ bias,
              const float* __restrict__ W1, const float* __restrict__ b1) {
    __shared__ unsigned long long wsp[64][64];
    __shared__ float4 zsh[64];
    __shared__ float2 tile2[32][66];
    __shared__ float4 sw1[64];
    __shared__ float4 bnp[32];
    __shared__ float red[256], red2[256];

    const int tid = threadIdx.x;
    const int c = tid & 63, q = tid >> 6;
    if (tid < 64) sw1[tid] = make_float4(W1[3 * tid], W1[3 * tid + 1],
                                         W1[3 * tid + 2], b1[tid]);
    if (tid < 32) bnp[tid] = make_float4(g_scale[0][2 * tid], g_shift[0][2 * tid],
                                         g_scale[0][2 * tid + 1], g_shift[0][2 * tid + 1]);
#pragma unroll
    for (int e = tid; e < 4096; e += 256) {
        int ci = e >> 6, cc = e & 63;
        float wv = W[cc * 64 + ci];
        wsp[ci][cc] = f2pack(wv, wv);
    }
    const unsigned long long bb2 = f2pack(bias[c], bias[c]);
    float s = 0.f, s2 = 0.f;
    __syncthreads();

    const float4* z4 = (const float4*)g_z;
    float2* yout = (float2*)g_y2;

    for (int tile = blockIdx.x; tile < NTILES; tile += gridDim.x) {
        if (tid < 64) zsh[tid] = z4[(size_t)tile * 64 + tid];
        __syncthreads();
#pragma unroll
        for (int rr = 0; rr < 4; rr++) {
            int e = tid + 256 * rr;
            int pair = e >> 5, ciq = e & 31;
            float4 xy = zsh[2 * pair];
            float4 zz = zsh[2 * pair + 1];
            float4 wv0 = sw1[2 * ciq], wv1 = sw1[2 * ciq + 1];
            float4 bn = bnp[ciq];
            float y00 = fmaf(wv0.x, xy.x, fmaf(wv0.y, xy.z, fmaf(wv0.z, zz.x, wv0.w)));
            float y01 = fmaf(wv0.x, xy.y, fmaf(wv0.y, xy.w, fmaf(wv0.z, zz.y, wv0.w)));
            float y10 = fmaf(wv1.x, xy.x, fmaf(wv1.y, xy.z, fmaf(wv1.z, zz.x, wv1.w)));
            float y11 = fmaf(wv1.x, xy.y, fmaf(wv1.y, xy.w, fmaf(wv1.z, zz.y, wv1.w)));
            float4 a;
            a.x = fmaxf(fmaf(y00, bn.x, bn.y), 0.f);
            a.y = fmaxf(fmaf(y01, bn.x, bn.y), 0.f);
            a.z = fmaxf(fmaf(y10, bn.z, bn.w), 0.f);
            a.w = fmaxf(fmaf(y11, bn.z, bn.w), 0.f);
            *(float4*)&tile2[pair][2 * ciq] = a;
        }
        __syncthreads();

        unsigned long long acc2[8];
#pragma unroll
        for (int m = 0; m < 8; m++) acc2[m] = bb2;
#pragma unroll
        for (int cq = 0; cq < 32; cq++) {
            unsigned long long wA = wsp[2 * cq][c];
            unsigned long long wB = wsp[2 * cq + 1][c];
#pragma unroll
            for (int m = 0; m < 8; m++) {
                ulonglong2 zv = *(const ulonglong2*)&tile2[q * 8 + m][2 * cq];
                FMA2(acc2[m], wA, zv.x, acc2[m]);
                FMA2(acc2[m], wB, zv.y, acc2[m]);
            }
        }

        float2* yo = yout + ((size_t)tile * 32 + q * 8) * 64 + c;
#pragma unroll
        for (int m = 0; m < 8; m++) {
            float a0, a1;
            f2unpack(acc2[m], a0, a1);
            yo[(size_t)m * 64] = make_float2(a0, a1);
            s += a0 + a1;
            s2 += a0 * a0 + a1 * a1;
        }
        __syncthreads();
    }

    red[tid] = s; red2[tid] = s2;
    __syncthreads();
    if (tid < 128) { red[tid] += red[tid + 128]; red2[tid] += red2[tid + 128]; }
    __syncthreads();
    if (tid < 64) {
        atomicAdd(&g_sum[1][tid], (double)(red[tid] + red[tid + 64]));
        atomicAdd(&g_sqs[1][tid], (double)(red2[tid] + red2[tid + 64]));
    }
}

// ---------------- layer 3: HMMA (mma.sync bf16-split) GEMM, fused BN2+ReLU/k-min-max ---
// Tile = one s-group: 32 positions x 128 channels, K=64. A = W in registers (hi/lo),
// B = activations bf16 hi/lo in shared (row = position, 72-half stride).
// 3 passes: Ah*Bh + Ah*Bl + Al*Bh into fp32 accumulators. 8 warps, warp w = 16 channels.
__global__ void __launch_bounds__(256, 2)
layer3_kernel(const float* __restrict__ W, const float* __restrict__ bias) {
    __shared__ __align__(16) unsigned short ah[32][72];
    __shared__ __align__(16) unsigned short al[32][72];
    __shared__ float ssc[64], ssh[64];

    const int tid = threadIdx.x;
    const int lane = tid & 31, w = tid >> 5;   // 8 warps
    const int g = lane >> 2, t = lane & 3;

    if (tid < 64) { ssc[tid] = g_scale[1][tid]; ssh[tid] = g_shift[1][tid]; }

    // A fragments from W (rows = channels w*16+g, +8), bf16 hi/lo split
    unsigned Ah[4][4], Al[4][4];
    {
        const float* w0 = W + (w * 16 + g) * 64;
        const float* w1 = W + (w * 16 + g + 8) * 64;
#pragma unroll
        for (int kk = 0; kk < 4; kk++) {
            int c0 = kk * 16 + 2 * t;
            float2 p00 = *(const float2*)(w0 + c0);
            float2 p01 = *(const float2*)(w0 + c0 + 8);
            float2 p10 = *(const float2*)(w1 + c0);
            float2 p11 = *(const float2*)(w1 + c0 + 8);
            Ah[kk][0] = bfsplit_pack(p00.x, p00.y, Al[kk][0]);
            Ah[kk][1] = bfsplit_pack(p10.x, p10.y, Al[kk][1]);
            Ah[kk][2] = bfsplit_pack(p01.x, p01.y, Al[kk][2]);
            Ah[kk][3] = bfsplit_pack(p11.x, p11.y, Al[kk][3]);
        }
    }
    const float biasA = bias[w * 16 + g];
    const float biasB = bias[w * 16 + g + 8];

    const uint32_t ah_base = smem_u32(&ah[0][0]);
    const uint32_t al_base = smem_u32(&al[0][0]);
    const uint32_t laddr = (uint32_t)((lane & 7) * 144 + (lane >> 3) * 16);

    const int pl = tid >> 4, cb = tid & 15;    // producer: pair pl, ci 4cb..4cb+3
    __syncthreads();
    float sc0 = ssc[4 * cb], sh0 = ssh[4 * cb];
    float sc1 = ssc[4 * cb + 1], sh1 = ssh[4 * cb + 1];
    float sc2 = ssc[4 * cb + 2], sh2 = ssh[4 * cb + 2];
    float sc3 = ssc[4 * cb + 3], sh3 = ssh[4 * cb + 3];

    const float2* y2p = (const float2*)g_y2;
    float sA = 0.f, s2A = 0.f, sB = 0.f, s2B = 0.f;

    for (int tile = blockIdx.x; tile < L3T; tile += gridDim.x) {
        // ---- producer: BN2+ReLU + bf16 split into shared ----
        {
            const float4* src = (const float4*)(y2p + ((size_t)(tile * 16 + pl)) * 64 + 4 * cb);
            float4 f0 = src[0];   // (ci0:pos0,pos1, ci1:pos0,pos1)
            float4 f1 = src[1];   // ci2, ci3
            float v00 = fmaxf(fmaf(f0.x, sc0, sh0), 0.f);
            float v10 = fmaxf(fmaf(f0.y, sc0, sh0), 0.f);
            float v01 = fmaxf(fmaf(f0.z, sc1, sh1), 0.f);
            float v11 = fmaxf(fmaf(f0.w, sc1, sh1), 0.f);
            float v02 = fmaxf(fmaf(f1.x, sc2, sh2), 0.f);
            float v12 = fmaxf(fmaf(f1.y, sc2, sh2), 0.f);
            float v03 = fmaxf(fmaf(f1.z, sc3, sh3), 0.f);
            float v13 = fmaxf(fmaf(f1.w, sc3, sh3), 0.f);
            uint2 h0, l0, h1, l1;
            h0.x = bfsplit_pack(v00, v01, l0.x);
            h0.y = bfsplit_pack(v02, v03, l0.y);
            h1.x = bfsplit_pack(v10, v11, l1.x);
            h1.y = bfsplit_pack(v12, v13, l1.y);
            *(uint2*)&ah[2 * pl][4 * cb]     = h0;
            *(uint2*)&ah[2 * pl + 1][4 * cb] = h1;
            *(uint2*)&al[2 * pl][4 * cb]     = l0;
            *(uint2*)&al[2 * pl + 1][4 * cb] = l1;
        }
        __syncthreads();

        float d[4][4];
#pragma unroll
        for (int nf = 0; nf < 4; nf++)
#pragma unroll
            for (int j = 0; j < 4; j++) d[nf][j] = 0.f;

        auto do_pass = [&](const unsigned (&A)[4][4], uint32_t bbase) {
#pragma unroll
            for (int kh = 0; kh < 2; kh++) {
#pragma unroll
                for (int nf = 0; nf < 4; nf++) {
                    uint32_t addr = bbase + laddr + (uint32_t)(nf * 8 * 144 + kh * 64);
                    unsigned b0, b1, b2, b3;
                    asm volatile(
                        "ldmatrix.sync.aligned.m8n8.x4.shared.b16 {%0,%1,%2,%3}, [%4];"
                        : "=r"(b0), "=r"(b1), "=r"(b2), "=r"(b3) : "r"(addr));
                    mma16816(d[nf], A[2 * kh],     b0, b1);
                    mma16816(d[nf], A[2 * kh + 1], b2, b3);
                }
            }
        };
        do_pass(Ah, ah_base);   // Ah * Bh
        do_pass(Ah, al_base);   // Ah * Bl
        do_pass(Al, ah_base);   // Al * Bh
        __syncthreads();        // smem reuse next tile

        // ---- epilogue: bias, stats, k-max/min (reduce over t-lanes) ----
        float mxA = -3.402823466e38f, mnA = 3.402823466e38f;
        float mxB = -3.402823466e38f, mnB = 3.402823466e38f;
#pragma unroll
        for (int nf = 0; nf < 4; nf++) {
            float vA0 = d[nf][0] + biasA, vA1 = d[nf][1] + biasA;
            float vB0 = d[nf][2] + biasB, vB1 = d[nf][3] + biasB;
            sA += vA0 + vA1; s2A += vA0 * vA0 + vA1 * vA1;
            sB += vB0 + vB1; s2B += vB0 * vB0 + vB1 * vB1;
            mxA = fmaxf(mxA, fmaxf(vA0, vA1)); mnA = fminf(mnA, fminf(vA0, vA1));
            mxB = fmaxf(mxB, fmaxf(vB0, vB1)); mnB = fminf(mnB, fminf(vB0, vB1));
        }
#pragma unroll
        for (int o = 1; o <= 2; o <<= 1) {
            mxA = fmaxf(mxA, __shfl_xor_sync(0xFFFFFFFFu, mxA, o));
            mnA = fminf(mnA, __shfl_xor_sync(0xFFFFFFFFu, mnA, o));
            mxB = fmaxf(mxB, __shfl_xor_sync(0xFFFFFFFFu, mxB, o));
            mnB = fminf(mnB, __shfl_xor_sync(0xFFFFFFFFu, mnB, o));
        }
        if (t == 0) {
            g_mm[(size_t)tile * 128 + w * 16 + g]     = make_float2(mxA, mnA);
            g_mm[(size_t)tile * 128 + w * 16 + g + 8] = make_float2(mxB, mnB);
        }
    }

#pragma unroll
    for (int o = 1; o <= 2; o <<= 1) {
        sA += __shfl_xor_sync(0xFFFFFFFFu, sA, o);
        s2A += __shfl_xor_sync(0xFFFFFFFFu, s2A, o);
        sB += __shfl_xor_sync(0xFFFFFFFFu, sB, o);
        s2B += __shfl_xor_sync(0xFFFFFFFFu, s2B, o);
    }
    if (t == 0) {
        atomicAdd(&g_sum[2][w * 16 + g],     (double)sA);
        atomicAdd(&g_sqs[2][w * 16 + g],     (double)s2A);
        atomicAdd(&g_sum[2][w * 16 + g + 8], (double)sB);
        atomicAdd(&g_sqs[2][w * 16 + g + 8], (double)s2B);
    }
}

// ---------------- BN finalize (layers 2,3) ----------------
__global__ void finalize_kernel(int l, const float* __restrict__ g,
                                const float* __restrict__ be, int C) {
    int c = threadIdx.x;
    if (c < C) {
        double n = (double)POSN;
        double m = g_sum[l][c] / n;
        double v = g_sqs[l][c] / n - m * m;
        if (v < 0.0) v = 0.0;
        float sc = g[c] * rsqrtf((float)v + 1e-5f);
        g_scale[l][c] = sc;
        g_shift[l][c] = be[c] - (float)m * sc;
    }
}

// ---------------- final: BN3+ReLU on max/min, transpose to [b,c,s] ----------------
__global__ void final_kernel(float* __restrict__ out) {
    __shared__ float tbuf[128 * 33];
    __shared__ float ssc[128], ssh[128];
    const int blk = blockIdx.x;
    const int b = blk >> 5, st = blk & 31;
    const int tid = threadIdx.x;
    if (tid < 128) { ssc[tid] = g_scale[2][tid]; ssh[tid] = g_shift[2][tid]; }
    __syncthreads();
#pragma unroll
    for (int rr = 0; rr < 16; rr++) {
        int e = tid + 256 * rr;
        int sl = e >> 7, cc = e & 127;
        float2 v = g_mm[((size_t)(b * NPT + st * 32 + sl)) * 128 + cc];
        float sc = ssc[cc], sh = ssh[cc];
        float val = (sc >= 0.f) ? fmaf(v.x, sc, sh) : fmaf(v.y, sc, sh);
        tbuf[cc * 33 + sl] = fmaxf(val, 0.f);
    }
    __syncthreads();
#pragma unroll
    for (int rr = 0; rr < 16; rr++) {
        int e = tid + 256 * rr;
        int c2 = e >> 5, s2 = e & 31;
        out[(size_t)(b * 128 + c2) * NPT + st * 32 + s2] = tbuf[c2 * 33 + s2];
    }
}

// ---------------- launch ----------------
extern "C" void kernel_launch(void* const* d_in, const int* in_sizes, int n_in,
                              void* d_out, int out_size) {
    const float* xyz   = (const float*)d_in[0];
    const int*   initf = (const int*)d_in[1];
    const float* W1 = (const float*)d_in[2];
    const float* b1 = (const float*)d_in[3];
    const float* g1 = (const float*)d_in[4];
    const float* be1 = (const float*)d_in[5];
    const float* W2 = (const float*)d_in[6];
    const float* b2 = (const float*)d_in[7];
    const float* g2 = (const float*)d_in[8];
    const float* be2 = (const float*)d_in[9];
    const float* W3 = (const float*)d_in[10];
    const float* b3 = (const float*)d_in[11];
    const float* g3 = (const float*)d_in[12];
    const float* be3 = (const float*)d_in[13];

    float* out = (float*)d_out;
    float* newxyz = out;                               // [16,1024,3]
    float* newpts = out + (size_t)BATCH * NPT * 3;     // [16,128,1024]

    fps_kernel<<<BATCH, 1024>>>(xyz, initf, newxyz);   // slot 1
    zero_stats_kernel<<<1, 512>>>();                   // slot 2
    noop_kernel<<<1, 32>>>();                          // slot 3
    knn_kernel<<<BATCH * 256, 128>>>(newxyz);          // slot 4 -> profiled
    group_kernel<<<NPAIR / 256, 256>>>(xyz, newxyz);
    finalize1_kernel<<<1, 64>>>(W1, b1, g1, be1);
    layer2_kernel<<<1184, 256>>>(W2, b2, W1, b1);
    finalize_kernel<<<1, 128>>>(1, g2, be2, 64);
    layer3_kernel<<<296, 256>>>(W3, b3);
    finalize_kernel<<<1, 128>>>(2, g3, be3, 128);
    final_kernel<<<512, 256>>>(newpts);
}

// round 14
// speedup vs baseline: 1.5438x; 1.1902x over previous
#include <cuda_runtime.h>
#include <cuda_bf16.h>
#include <cstdint>

#define BATCH  16
#define NPTS   4096
#define NPT    1024
#define KNN    32
#define POSN   (BATCH*NPT*KNN)   // 524288 positions
#define NPAIR  (POSN/2)          // 262144 pairs
#define NTILES (POSN/64)         // 8192 layer2 tiles (64 positions)
#define L3T    (BATCH*NPT)       // 16384 layer3 tiles (one s-group = 32 positions)

// ---------------- scratch (device globals; no allocations allowed) ----------------
__device__ int    g_knn[POSN];
__device__ float  g_z[(size_t)POSN * 4];
__device__ float  g_y2[(size_t)POSN * 64];        // [NPAIR][64] float2 (pair-major)
__device__ float2 g_mm[(size_t)BATCH * NPT * 128];// per (b,s,c): (max_k, min_k) of pre-BN y3
__device__ double g_mom[9];
__device__ double g_sum[3][128];
__device__ double g_sqs[3][128];
__device__ float  g_scale[3][128];
__device__ float  g_shift[3][128];

// ---- f32x2 helpers ----
__device__ __forceinline__ unsigned long long f2pack(float a, float b) {
    unsigned long long v;
    asm("mov.b64 %0, {%1, %2};" : "=l"(v) : "f"(a), "f"(b));
    return v;
}
__device__ __forceinline__ void f2unpack(unsigned long long v, float& a, float& b) {
    asm("mov.b64 {%0, %1}, %2;" : "=f"(a), "=f"(b) : "l"(v));
}
#define ADD2(d, a, b) \
    asm("add.rn.f32x2 %0, %1, %2;" : "=l"(d) : "l"(a), "l"(b))
#define MUL2(d, a, b) \
    asm("mul.rn.f32x2 %0, %1, %2;" : "=l"(d) : "l"(a), "l"(b))

__device__ __forceinline__ uint32_t smem_u32(const void* p) {
    uint32_t a;
    asm("{ .reg .u64 t; cvta.to.shared.u64 t, %1; cvt.u32.u64 %0, t; }"
        : "=r"(a) : "l"(p));
    return a;
}

// bf16 hi/lo split: returns packed (hi(a),hi(b)); lo_pack = (lo(a),lo(b))
__device__ __forceinline__ unsigned bfsplit_pack(float a, float b, unsigned& lo_pack) {
    __nv_bfloat16 ha = __float2bfloat16(a), hb = __float2bfloat16(b);
    __nv_bfloat16 la = __float2bfloat16(a - __bfloat162float(ha));
    __nv_bfloat16 lb = __float2bfloat16(b - __bfloat162float(hb));
    lo_pack = (unsigned)__bfloat16_as_ushort(la) |
              ((unsigned)__bfloat16_as_ushort(lb) << 16);
    return (unsigned)__bfloat16_as_ushort(ha) |
           ((unsigned)__bfloat16_as_ushort(hb) << 16);
}

// m16n8k16 bf16 mma, fp32 accumulate (baseline PTX, sm_80+)
__device__ __forceinline__ void mma16816(float d[4], const unsigned a[4],
                                         unsigned b0, unsigned b1) {
    asm volatile(
        "mma.sync.aligned.m16n8k16.row.col.f32.bf16.bf16.f32 "
        "{%0,%1,%2,%3}, {%4,%5,%6,%7}, {%8,%9}, {%0,%1,%2,%3};"
        : "+f"(d[0]), "+f"(d[1]), "+f"(d[2]), "+f"(d[3])
        : "r"(a[0]), "r"(a[1]), "r"(a[2]), "r"(a[3]), "r"(b0), "r"(b1));
}

#define LDMATRIX_X4(b0, b1, b2, b3, addr) \
    asm volatile("ldmatrix.sync.aligned.m8n8.x4.shared.b16 {%0,%1,%2,%3}, [%4];" \
                 : "=r"(b0), "=r"(b1), "=r"(b2), "=r"(b3) : "r"(addr))

// ---------------- no-op (launch-slot alignment) ----------------
__global__ void noop_kernel() {}

// ---------------- zero stats ----------------
__global__ void zero_stats_kernel() {
    int t = threadIdx.x;           // 512 threads
    if (t < 128)      { g_sum[1][t] = 0.0;       g_sqs[1][t] = 0.0; }
    else if (t < 256) { g_sum[2][t - 128] = 0.0; g_sqs[2][t - 128] = 0.0; }
    if (t < 9) g_mom[t] = 0.0;
}

// ---------------- farthest point sampling (1024 thr, 4 pts/thread) ----------------
__global__ void fps_kernel(const float* __restrict__ xyz,
                           const int* __restrict__ initf,
                           float* __restrict__ newxyz) {
    __shared__ unsigned wkd[2][32], wki[2][32];

    const int b = blockIdx.x, tid = threadIdx.x;
    const int lane = tid & 31, w = tid >> 5;
    const float* xb = xyz + (size_t)b * NPTS * 3;

    unsigned long long px2[2], py2[2], pz2[2];
    float dist[4];
#pragma unroll
    for (int u = 0; u < 2; u++) {
        int p0 = tid + 1024 * (2 * u);
        int p1 = tid + 1024 * (2 * u + 1);
        px2[u] = f2pack(xb[3 * p0 + 0], xb[3 * p1 + 0]);
        py2[u] = f2pack(xb[3 * p0 + 1], xb[3 * p1 + 1]);
        pz2[u] = f2pack(xb[3 * p0 + 2], xb[3 * p1 + 2]);
        dist[2 * u] = 1e10f; dist[2 * u + 1] = 1e10f;
    }
    int f = initf[b];
    __syncthreads();

    for (int it = 0; it < NPT; it++) {
        float cx = xb[3 * f + 0], cy = xb[3 * f + 1], cz = xb[3 * f + 2];
        if (tid == 0) {
            float* o = newxyz + (size_t)(b * NPT + it) * 3;
            o[0] = cx; o[1] = cy; o[2] = cz;
        }
        unsigned long long ncx = f2pack(-cx, -cx);
        unsigned long long ncy = f2pack(-cy, -cy);
        unsigned long long ncz = f2pack(-cz, -cz);

#pragma unroll
        for (int u = 0; u < 2; u++) {
            unsigned long long dx, dy, dz, xx, yy, zz, ss, dd;
            ADD2(dx, px2[u], ncx);
            ADD2(dy, py2[u], ncy);
            ADD2(dz, pz2[u], ncz);
            MUL2(xx, dx, dx);
            MUL2(yy, dy, dy);
            MUL2(zz, dz, dz);
            ADD2(ss, xx, yy);
            ADD2(dd, ss, zz);
            float d0, d1;
            f2unpack(dd, d0, d1);
            dist[2 * u]     = fminf(dist[2 * u], d0);
            dist[2 * u + 1] = fminf(dist[2 * u + 1], d1);
        }
        float dmax = fmaxf(fmaxf(dist[0], dist[1]), fmaxf(dist[2], dist[3]));
        unsigned mw = __reduce_max_sync(0xFFFFFFFFu, __float_as_uint(dmax));
        unsigned ic[4];
#pragma unroll
        for (int j = 0; j < 4; j++)
            ic[j] = (__float_as_uint(dist[j]) == mw)
                      ? (unsigned)(tid + 1024 * j) : 0xFFFFFFFFu;
        unsigned widx = __reduce_min_sync(0xFFFFFFFFu,
                          umin(umin(ic[0], ic[1]), umin(ic[2], ic[3])));

        if (lane == 0) { wkd[it & 1][w] = mw; wki[it & 1][w] = widx; }
        __syncthreads();
        unsigned dl = wkd[it & 1][lane];
        unsigned il = wki[it & 1][lane];
        unsigned dm = __reduce_max_sync(0xFFFFFFFFu, dl);
        unsigned cand = (dl == dm) ? il : 0xFFFFFFFFu;
        f = (int)__reduce_min_sync(0xFFFFFFFFu, cand);
    }
}

// ---------------- kNN (top-33 smallest, drop rank 0) ----------------
__global__ void knn_kernel(const float* __restrict__ newxyz) {
    __shared__ unsigned long long sl[128][33];
    float* qx = (float*)&sl[0][0];
    float* qy = qx + NPT;
    float* qz = qy + NPT;

    const int tid = threadIdx.x, lane = tid & 31, w = tid >> 5;
    const int b = blockIdx.x >> 8;
    const int s = ((blockIdx.x & 255) << 2) | w;
    const float* nb = newxyz + (size_t)b * NPT * 3;

    for (int i = tid; i < NPT; i += 128) {
        qx[i] = nb[3 * i + 0];
        qy[i] = nb[3 * i + 1];
        qz[i] = nb[3 * i + 2];
    }
    __syncthreads();

    const float x = qx[s], y = qy[s], z = qz[s];

    unsigned long long r[32];
#pragma unroll
    for (int u = 0; u < 32; u++) {
        int j = lane + 32 * u;
        float dx = __fsub_rn(qx[j], x);
        float dy = __fsub_rn(qy[j], y);
        float dz = __fsub_rn(qz[j], z);
        float d = __fadd_rn(__fadd_rn(__fmul_rn(dx, dx), __fmul_rn(dy, dy)),
                            __fmul_rn(dz, dz));
        r[u] = ((unsigned long long)__float_as_uint(d) << 32) | (unsigned)j;
    }
    __syncthreads();

#pragma unroll
    for (int k = 2; k <= 32; k <<= 1) {
#pragma unroll
        for (int j = k >> 1; j > 0; j >>= 1) {
#pragma unroll
            for (int i = 0; i < 32; i++) {
                int ixj = i ^ j;
                if (ixj > i) {
                    bool up = ((i & k) == 0);
                    unsigned long long a = r[i], bb = r[ixj];
                    if ((a > bb) == up) { r[i] = bb; r[ixj] = a; }
                }
            }
        }
    }

#pragma unroll
    for (int u = 2; u < 32; u++) sl[tid][u] = r[u];

    unsigned ch = (unsigned)(r[0] >> 32), cl = (unsigned)r[0];
    unsigned nh = (unsigned)(r[1] >> 32), nl = (unsigned)r[1];
    int h = 2;
    int myidx = 0;
    for (int t = 0; t < 33; t++) {
        unsigned dm = __reduce_min_sync(0xFFFFFFFFu, ch);
        unsigned jc = (ch == dm) ? cl : 0xFFFFFFFFu;
        unsigned jm = __reduce_min_sync(0xFFFFFFFFu, jc);
        if (t && lane == t - 1) myidx = (int)jm;
        if (ch == dm && cl == jm) {
            ch = nh; cl = nl;
            if (h < 32) {
                unsigned long long nx = sl[tid][h];
                nh = (unsigned)(nx >> 32);
                nl = (unsigned)nx;
            } else {
                nh = 0xFFFFFFFFu;
                nl = 0xFFFFFFFFu;
            }
            h++;
        }
    }
    g_knn[(size_t)(b * NPT + s) * KNN + lane] = myidx;
}

// ---------------- grouping: gather z = xyz[knn] - center, 9 moments ----------------
__global__ void group_kernel(const float* __restrict__ xyz,
                             const float* __restrict__ newxyz) {
    __shared__ float wm[8][9];
    const int i = blockIdx.x * 256 + threadIdx.x;
    int2 jj = ((const int2*)g_knn)[i];
    int bs = i >> 4;
    int b = bs >> 10;
    const float* np = newxyz + (size_t)bs * 3;
    float nx = np[0], ny = np[1], nz = np[2];
    const float* p0 = xyz + (size_t)(b * NPTS + jj.x) * 3;
    const float* p1 = xyz + (size_t)(b * NPTS + jj.y) * 3;
    float x0 = p0[0] - nx, y0 = p0[1] - ny, z0 = p0[2] - nz;
    float x1 = p1[0] - nx, y1 = p1[1] - ny, z1 = p1[2] - nz;
    float4* z4 = (float4*)g_z;
    z4[2 * i]     = make_float4(x0, x1, y0, y1);
    z4[2 * i + 1] = make_float4(z0, z1, 0.f, 0.f);

    float m[9] = { x0 + x1, y0 + y1, z0 + z1,
                   x0 * x0 + x1 * x1, y0 * y0 + y1 * y1, z0 * z0 + z1 * z1,
                   x0 * y0 + x1 * y1, x0 * z0 + x1 * z1, y0 * z0 + y1 * z1 };
#pragma unroll
    for (int u = 0; u < 9; u++) {
        float v = m[u];
#pragma unroll
        for (int o = 16; o; o >>= 1) v += __shfl_xor_sync(0xFFFFFFFFu, v, o);
        if ((threadIdx.x & 31) == 0) wm[threadIdx.x >> 5][u] = v;
    }
    __syncthreads();
    if (threadIdx.x < 9) {
        float s = 0.f;
#pragma unroll
        for (int ww = 0; ww < 8; ww++) s += wm[ww][threadIdx.x];
        atomicAdd(&g_mom[threadIdx.x], (double)s);
    }
}

// ---------------- BN1 stats from moments ----------------
__global__ void finalize1_kernel(const float* __restrict__ W1,
                                 const float* __restrict__ b1,
                                 const float* __restrict__ g1,
                                 const float* __restrict__ be1) {
    int c = threadIdx.x;   // 64
    double w0 = W1[3 * c], w1 = W1[3 * c + 1], w2 = W1[3 * c + 2], b = b1[c];
    double Sx = g_mom[0], Sy = g_mom[1], Sz = g_mom[2];
    double Sxx = g_mom[3], Syy = g_mom[4], Szz = g_mom[5];
    double Sxy = g_mom[6], Sxz = g_mom[7], Syz = g_mom[8];
    double N = (double)POSN;
    double ws = w0 * Sx + w1 * Sy + w2 * Sz;
    double mean = (ws + N * b) / N;
    double ey2 = (w0 * w0 * Sxx + w1 * w1 * Syy + w2 * w2 * Szz
                + 2.0 * (w0 * w1 * Sxy + w0 * w2 * Sxz + w1 * w2 * Syz)
                + 2.0 * b * ws + N * b * b) / N;
    double var = ey2 - mean * mean;
    if (var < 0.0) var = 0.0;
    float sc = g1[c] * rsqrtf((float)var + 1e-5f);
    g_scale[0][c] = sc;
    g_shift[0][c] = be1[c] - (float)mean * sc;
}

// ---------------- layer 2: HMMA bf16-split GEMM (y1 recompute fused into producer) ----
// Tile = 64 positions x 64 channels, K=64. Warp w: channels (w&3)*16, pos-half (w>>2)*32.
// Producer: y1 = (sc*W1)·z + (sc*b1+sh), ReLU, bf16 hi/lo split into shared
// (row = position, 72-half stride). 3 passes AhBh+AhBl+AlBh, fp32 accum.
// Epilogue: C col n = position nf*8+2t(+1) (consecutive pair) -> float2 store to g_y2.
__global__ void __launch_bounds__(256, 2)
layer2_kernel(const float* __restrict__ W, const float* __restrict__ bias,
              const float* __restrict__ W1, const float* __restrict__ b1) {
    __shared__ __align__(16) unsigned short ah[64][72];
    __shared__ __align__(16) unsigned short al[64][72];
    __shared__ float4 sw1f[64];   // fused (sc*w0, sc*w1, sc*w2, sc*b + sh)

    const int tid = threadIdx.x;
    const int lane = tid & 31, w = tid >> 5;
    const int g = lane >> 2, t = lane & 3;
    const int ph = w >> 2, cq = w & 3;

    if (tid < 64) {
        float sc = g_scale[0][tid], sh = g_shift[0][tid];
        sw1f[tid] = make_float4(sc * W1[3 * tid], sc * W1[3 * tid + 1],
                                sc * W1[3 * tid + 2], fmaf(sc, b1[tid], sh));
    }

    // A fragments from W2 rows cq*16+g, cq*16+g+8 (bf16 hi/lo)
    unsigned Ah[4][4], Al[4][4];
    {
        const float* w0p = W + (cq * 16 + g) * 64;
        const float* w1p = W + (cq * 16 + g + 8) * 64;
#pragma unroll
        for (int kk = 0; kk < 4; kk++) {
            int c0 = kk * 16 + 2 * t;
            float2 p00 = *(const float2*)(w0p + c0);
            float2 p01 = *(const float2*)(w0p + c0 + 8);
            float2 p10 = *(const float2*)(w1p + c0);
            float2 p11 = *(const float2*)(w1p + c0 + 8);
            Ah[kk][0] = bfsplit_pack(p00.x, p00.y, Al[kk][0]);
            Ah[kk][1] = bfsplit_pack(p10.x, p10.y, Al[kk][1]);
            Ah[kk][2] = bfsplit_pack(p01.x, p01.y, Al[kk][2]);
            Ah[kk][3] = bfsplit_pack(p11.x, p11.y, Al[kk][3]);
        }
    }
    const float biasA = bias[cq * 16 + g];
    const float biasB = bias[cq * 16 + g + 8];

    const uint32_t ah_base = smem_u32(&ah[0][0]) + (uint32_t)(ph * 32 * 144);
    const uint32_t al_base = smem_u32(&al[0][0]) + (uint32_t)(ph * 32 * 144);
    const uint32_t laddr = (uint32_t)((lane & 7) * 144 + (lane >> 3) * 16);

    const int pl = tid >> 3, cb = tid & 7;   // producer: pair pl, channels 8cb..8cb+7
    __syncthreads();
    float4 wf[8];
#pragma unroll
    for (int i = 0; i < 8; i++) wf[i] = sw1f[8 * cb + i];

    const float4* z4 = (const float4*)g_z;
    float2* y2p = (float2*)g_y2;
    float sA = 0.f, s2A = 0.f, sB = 0.f, s2B = 0.f;

    for (int tile = blockIdx.x; tile < NTILES; tile += gridDim.x) {
        // ---- producer: y1 recompute + ReLU + bf16 split ----
        {
            float4 xy = z4[(size_t)(tile * 32 + pl) * 2];       // x0,x1,y0,y1
            float4 zz = z4[(size_t)(tile * 32 + pl) * 2 + 1];   // z0,z1,-,-
            unsigned h0[4], l0[4], h1[4], l1[4];
#pragma unroll
            for (int i = 0; i < 4; i++) {
                float4 wa = wf[2 * i], wb = wf[2 * i + 1];
                float va0 = fmaxf(fmaf(wa.x, xy.x, fmaf(wa.y, xy.z, fmaf(wa.z, zz.x, wa.w))), 0.f);
                float va1 = fmaxf(fmaf(wa.x, xy.y, fmaf(wa.y, xy.w, fmaf(wa.z, zz.y, wa.w))), 0.f);
                float vb0 = fmaxf(fmaf(wb.x, xy.x, fmaf(wb.y, xy.z, fmaf(wb.z, zz.x, wb.w))), 0.f);
                float vb1 = fmaxf(fmaf(wb.x, xy.y, fmaf(wb.y, xy.w, fmaf(wb.z, zz.y, wb.w))), 0.f);
                h0[i] = bfsplit_pack(va0, vb0, l0[i]);
                h1[i] = bfsplit_pack(va1, vb1, l1[i]);
            }
            *(uint4*)&ah[2 * pl][8 * cb]     = make_uint4(h0[0], h0[1], h0[2], h0[3]);
            *(uint4*)&ah[2 * pl + 1][8 * cb] = make_uint4(h1[0], h1[1], h1[2], h1[3]);
            *(uint4*)&al[2 * pl][8 * cb]     = make_uint4(l0[0], l0[1], l0[2], l0[3]);
            *(uint4*)&al[2 * pl + 1][8 * cb] = make_uint4(l1[0], l1[1], l1[2], l1[3]);
        }
        __syncthreads();

        float d[4][4];
#pragma unroll
        for (int nf = 0; nf < 4; nf++)
#pragma unroll
            for (int j = 0; j < 4; j++) d[nf][j] = 0.f;

        auto do_pass = [&](const unsigned (&A)[4][4], uint32_t bbase) {
#pragma unroll
            for (int kh = 0; kh < 2; kh++) {
#pragma unroll
                for (int nf = 0; nf < 4; nf++) {
                    uint32_t addr = bbase + laddr + (uint32_t)(nf * 8 * 144 + kh * 64);
                    unsigned b0, b1, b2, b3;
                    LDMATRIX_X4(b0, b1, b2, b3, addr);
                    mma16816(d[nf], A[2 * kh],     b0, b1);
                    mma16816(d[nf], A[2 * kh + 1], b2, b3);
                }
            }
        };
        do_pass(Ah, ah_base);   // Ah * Bh
        do_pass(Ah, al_base);   // Ah * Bl
        do_pass(Al, ah_base);   // Al * Bh
        __syncthreads();        // smem reused next tile

        // ---- epilogue: bias, store y2 (consecutive position pair), stats ----
#pragma unroll
        for (int nf = 0; nf < 4; nf++) {
            size_t pair = (size_t)tile * 32 + ph * 16 + nf * 4 + t;
            float vA0 = d[nf][0] + biasA, vA1 = d[nf][1] + biasA;
            float vB0 = d[nf][2] + biasB, vB1 = d[nf][3] + biasB;
            y2p[pair * 64 + cq * 16 + g]     = make_float2(vA0, vA1);
            y2p[pair * 64 + cq * 16 + g + 8] = make_float2(vB0, vB1);
            sA += vA0 + vA1; s2A += vA0 * vA0 + vA1 * vA1;
            sB += vB0 + vB1; s2B += vB0 * vB0 + vB1 * vB1;
        }
    }

#pragma unroll
    for (int o = 1; o <= 2; o <<= 1) {
        sA += __shfl_xor_sync(0xFFFFFFFFu, sA, o);
        s2A += __shfl_xor_sync(0xFFFFFFFFu, s2A, o);
        sB += __shfl_xor_sync(0xFFFFFFFFu, sB, o);
        s2B += __shfl_xor_sync(0xFFFFFFFFu, s2B, o);
    }
    if (t == 0) {
        atomicAdd(&g_sum[1][cq * 16 + g],     (double)sA);
        atomicAdd(&g_sqs[1][cq * 16 + g],     (double)s2A);
        atomicAdd(&g_sum[1][cq * 16 + g + 8], (double)sB);
        atomicAdd(&g_sqs[1][cq * 16 + g + 8], (double)s2B);
    }
}

// ---------------- layer 3: HMMA bf16-split GEMM, fused BN2+ReLU / k-min-max ----------
__global__ void __launch_bounds__(256, 2)
layer3_kernel(const float* __restrict__ W, const float* __restrict__ bias) {
    __shared__ __align__(16) unsigned short ah[32][72];
    __shared__ __align__(16) unsigned short al[32][72];
    __shared__ float ssc[64], ssh[64];

    const int tid = threadIdx.x;
    const int lane = tid & 31, w = tid >> 5;   // 8 warps
    const int g = lane >> 2, t = lane & 3;

    if (tid < 64) { ssc[tid] = g_scale[1][tid]; ssh[tid] = g_shift[1][tid]; }

    unsigned Ah[4][4], Al[4][4];
    {
        const float* w0 = W + (w * 16 + g) * 64;
        const float* w1 = W + (w * 16 + g + 8) * 64;
#pragma unroll
        for (int kk = 0; kk < 4; kk++) {
            int c0 = kk * 16 + 2 * t;
            float2 p00 = *(const float2*)(w0 + c0);
            float2 p01 = *(const float2*)(w0 + c0 + 8);
            float2 p10 = *(const float2*)(w1 + c0);
            float2 p11 = *(const float2*)(w1 + c0 + 8);
            Ah[kk][0] = bfsplit_pack(p00.x, p00.y, Al[kk][0]);
            Ah[kk][1] = bfsplit_pack(p10.x, p10.y, Al[kk][1]);
            Ah[kk][2] = bfsplit_pack(p01.x, p01.y, Al[kk][2]);
            Ah[kk][3] = bfsplit_pack(p11.x, p11.y, Al[kk][3]);
        }
    }
    const float biasA = bias[w * 16 + g];
    const float biasB = bias[w * 16 + g + 8];

    const uint32_t ah_base = smem_u32(&ah[0][0]);
    const uint32_t al_base = smem_u32(&al[0][0]);
    const uint32_t laddr = (uint32_t)((lane & 7) * 144 + (lane >> 3) * 16);

    const int pl = tid >> 4, cb = tid & 15;    // producer: pair pl, ci 4cb..4cb+3
    __syncthreads();
    float sc0 = ssc[4 * cb], sh0 = ssh[4 * cb];
    float sc1 = ssc[4 * cb + 1], sh1 = ssh[4 * cb + 1];
    float sc2 = ssc[4 * cb + 2], sh2 = ssh[4 * cb + 2];
    float sc3 = ssc[4 * cb + 3], sh3 = ssh[4 * cb + 3];

    const float2* y2p = (const float2*)g_y2;
    float sA = 0.f, s2A = 0.f, sB = 0.f, s2B = 0.f;

    for (int tile = blockIdx.x; tile < L3T; tile += gridDim.x) {
        {
            const float4* src = (const float4*)(y2p + ((size_t)(tile * 16 + pl)) * 64 + 4 * cb);
            float4 f0 = src[0];
            float4 f1 = src[1];
            float v00 = fmaxf(fmaf(f0.x, sc0, sh0), 0.f);
            float v10 = fmaxf(fmaf(f0.y, sc0, sh0), 0.f);
            float v01 = fmaxf(fmaf(f0.z, sc1, sh1), 0.f);
            float v11 = fmaxf(fmaf(f0.w, sc1, sh1), 0.f);
            float v02 = fmaxf(fmaf(f1.x, sc2, sh2), 0.f);
            float v12 = fmaxf(fmaf(f1.y, sc2, sh2), 0.f);
            float v03 = fmaxf(fmaf(f1.z, sc3, sh3), 0.f);
            float v13 = fmaxf(fmaf(f1.w, sc3, sh3), 0.f);
            uint2 h0, l0, h1, l1;
            h0.x = bfsplit_pack(v00, v01, l0.x);
            h0.y = bfsplit_pack(v02, v03, l0.y);
            h1.x = bfsplit_pack(v10, v11, l1.x);
            h1.y = bfsplit_pack(v12, v13, l1.y);
            *(uint2*)&ah[2 * pl][4 * cb]     = h0;
            *(uint2*)&ah[2 * pl + 1][4 * cb] = h1;
            *(uint2*)&al[2 * pl][4 * cb]     = l0;
            *(uint2*)&al[2 * pl + 1][4 * cb] = l1;
        }
        __syncthreads();

        float d[4][4];
#pragma unroll
        for (int nf = 0; nf < 4; nf++)
#pragma unroll
            for (int j = 0; j < 4; j++) d[nf][j] = 0.f;

        auto do_pass = [&](const unsigned (&A)[4][4], uint32_t bbase) {
#pragma unroll
            for (int kh = 0; kh < 2; kh++) {
#pragma unroll
                for (int nf = 0; nf < 4; nf++) {
                    uint32_t addr = bbase + laddr + (uint32_t)(nf * 8 * 144 + kh * 64);
                    unsigned b0, b1, b2, b3;
                    LDMATRIX_X4(b0, b1, b2, b3, addr);
                    mma16816(d[nf], A[2 * kh],     b0, b1);
                    mma16816(d[nf], A[2 * kh + 1], b2, b3);
                }
            }
        };
        do_pass(Ah, ah_base);
        do_pass(Ah, al_base);
        do_pass(Al, ah_base);
        __syncthreads();

        float mxA = -3.402823466e38f, mnA = 3.402823466e38f;
        float mxB = -3.402823466e38f, mnB = 3.402823466e38f;
#pragma unroll
        for (int nf = 0; nf < 4; nf++) {
            float vA0 = d[nf][0] + biasA, vA1 = d[nf][1] + biasA;
            float vB0 = d[nf][2] + biasB, vB1 = d[nf][3] + biasB;
            sA += vA0 + vA1; s2A += vA0 * vA0 + vA1 * vA1;
            sB += vB0 + vB1; s2B += vB0 * vB0 + vB1 * vB1;
            mxA = fmaxf(mxA, fmaxf(vA0, vA1)); mnA = fminf(mnA, fminf(vA0, vA1));
            mxB = fmaxf(mxB, fmaxf(vB0, vB1)); mnB = fminf(mnB, fminf(vB0, vB1));
        }
#pragma unroll
        for (int o = 1; o <= 2; o <<= 1) {
            mxA = fmaxf(mxA, __shfl_xor_sync(0xFFFFFFFFu, mxA, o));
            mnA = fminf(mnA, __shfl_xor_sync(0xFFFFFFFFu, mnA, o));
            mxB = fmaxf(mxB, __shfl_xor_sync(0xFFFFFFFFu, mxB, o));
            mnB = fminf(mnB, __shfl_xor_sync(0xFFFFFFFFu, mnB, o));
        }
        if (t == 0) {
            g_mm[(size_t)tile * 128 + w * 16 + g]     = make_float2(mxA, mnA);
            g_mm[(size_t)tile * 128 + w * 16 + g + 8] = make_float2(mxB, mnB);
        }
    }

#pragma unroll
    for (int o = 1; o <= 2; o <<= 1) {
        sA += __shfl_xor_sync(0xFFFFFFFFu, sA, o);
        s2A += __shfl_xor_sync(0xFFFFFFFFu, s2A, o);
        sB += __shfl_xor_sync(0xFFFFFFFFu, sB, o);
        s2B += __shfl_xor_sync(0xFFFFFFFFu, s2B, o);
    }
    if (t == 0) {
        atomicAdd(&g_sum[2][w * 16 + g],     (double)sA);
        atomicAdd(&g_sqs[2][w * 16 + g],     (double)s2A);
        atomicAdd(&g_sum[2][w * 16 + g + 8], (double)sB);
        atomicAdd(&g_sqs[2][w * 16 + g + 8], (double)s2B);
    }
}

// ---------------- BN finalize (layers 2,3) ----------------
__global__ void finalize_kernel(int l, const float* __restrict__ g,
                                const float* __restrict__ be, int C) {
    int c = threadIdx.x;
    if (c < C) {
        double n = (double)POSN;
        double m = g_sum[l][c] / n;
        double v = g_sqs[l][c] / n - m * m;
        if (v < 0.0) v = 0.0;
        float sc = g[c] * rsqrtf((float)v + 1e-5f);
        g_scale[l][c] = sc;
        g_shift[l][c] = be[c] - (float)m * sc;
    }
}

// ---------------- final: BN3+ReLU on max/min, transpose to [b,c,s] ----------------
__global__ void final_kernel(float* __restrict__ out) {
    __shared__ float tbuf[128 * 33];
    __shared__ float ssc[128], ssh[128];
    const int blk = blockIdx.x;
    const int b = blk >> 5, st = blk & 31;
    const int tid = threadIdx.x;
    if (tid < 128) { ssc[tid] = g_scale[2][tid]; ssh[tid] = g_shift[2][tid]; }
    __syncthreads();
#pragma unroll
    for (int rr = 0; rr < 16; rr++) {
        int e = tid + 256 * rr;
        int sl = e >> 7, cc = e & 127;
        float2 v = g_mm[((size_t)(b * NPT + st * 32 + sl)) * 128 + cc];
        float sc = ssc[cc], sh = ssh[cc];
        float val = (sc >= 0.f) ? fmaf(v.x, sc, sh) : fmaf(v.y, sc, sh);
        tbuf[cc * 33 + sl] = fmaxf(val, 0.f);
    }
    __syncthreads();
#pragma unroll
    for (int rr = 0; rr < 16; rr++) {
        int e = tid + 256 * rr;
        int c2 = e >> 5, s2 = e & 31;
        out[(size_t)(b * 128 + c2) * NPT + st * 32 + s2] = tbuf[c2 * 33 + s2];
    }
}

// ---------------- launch ----------------
extern "C" void kernel_launch(void* const* d_in, const int* in_sizes, int n_in,
                              void* d_out, int out_size) {
    const float* xyz   = (const float*)d_in[0];
    const int*   initf = (const int*)d_in[1];
    const float* W1 = (const float*)d_in[2];
    const float* b1 = (const float*)d_in[3];
    const float* g1 = (const float*)d_in[4];
    const float* be1 = (const float*)d_in[5];
    const float* W2 = (const float*)d_in[6];
    const float* b2 = (const float*)d_in[7];
    const float* g2 = (const float*)d_in[8];
    const float* be2 = (const float*)d_in[9];
    const float* W3 = (const float*)d_in[10];
    const float* b3 = (const float*)d_in[11];
    const float* g3 = (const float*)d_in[12];
    const float* be3 = (const float*)d_in[13];

    float* out = (float*)d_out;
    float* newxyz = out;                               // [16,1024,3]
    float* newpts = out + (size_t)BATCH * NPT * 3;     // [16,128,1024]

    fps_kernel<<<BATCH, 1024>>>(xyz, initf, newxyz);   // slot 1
    zero_stats_kernel<<<1, 512>>>();                   // slot 2
    noop_kernel<<<1, 32>>>();                          // slot 3
    knn_kernel<<<BATCH * 256, 128>>>(newxyz);          // slot 4 -> profiled
    group_kernel<<<NPAIR / 256, 256>>>(xyz, newxyz);
    finalize1_kernel<<<1, 64>>>(W1, b1, g1, be1);
    layer2_kernel<<<296, 256>>>(W2, b2, W1, b1);
    finalize_kernel<<<1, 128>>>(1, g2, be2, 64);
    layer3_kernel<<<296, 256>>>(W3, b3);
    finalize_kernel<<<1, 128>>>(2, g3, be3, 128);
    final_kernel<<<512, 256>>>(newpts);
}

// round 16
// speedup vs baseline: 1.5967x; 1.0343x over previous
#include <cuda_runtime.h>
#include <cuda_bf16.h>
#include <cstdint>

#define BATCH  16
#define NPTS   4096
#define NPT    1024
#define KNN    32
#define POSN   (BATCH*NPT*KNN)   // 524288 positions
#define NPAIR  (POSN/2)          // 262144 pairs
#define NTILES (POSN/64)         // 8192 layer2 tiles (64 positions)
#define L3T    (BATCH*NPT)       // 16384 layer3 tiles (one s-group = 32 positions)

// ---------------- scratch (device globals; no allocations allowed) ----------------
__device__ int    g_knn[POSN];
__device__ float  g_z[(size_t)POSN * 4];
__device__ float  g_y2[(size_t)POSN * 64];        // [NPAIR][64] float2 (pair-major)
__device__ float2 g_mm[(size_t)BATCH * NPT * 128];// per (b,s,c): (max_k, min_k) of pre-BN y3
__device__ double g_mom[9];
__device__ double g_sum[3][128];
__device__ double g_sqs[3][128];
__device__ float  g_scale[3][128];
__device__ float  g_shift[3][128];

// ---- f32x2 helpers ----
__device__ __forceinline__ unsigned long long f2pack(float a, float b) {
    unsigned long long v;
    asm("mov.b64 %0, {%1, %2};" : "=l"(v) : "f"(a), "f"(b));
    return v;
}
__device__ __forceinline__ void f2unpack(unsigned long long v, float& a, float& b) {
    asm("mov.b64 {%0, %1}, %2;" : "=f"(a), "=f"(b) : "l"(v));
}
#define ADD2(d, a, b) \
    asm("add.rn.f32x2 %0, %1, %2;" : "=l"(d) : "l"(a), "l"(b))
#define MUL2(d, a, b) \
    asm("mul.rn.f32x2 %0, %1, %2;" : "=l"(d) : "l"(a), "l"(b))

__device__ __forceinline__ uint32_t smem_u32(const void* p) {
    uint32_t a;
    asm("{ .reg .u64 t; cvta.to.shared.u64 t, %1; cvt.u32.u64 %0, t; }"
        : "=r"(a) : "l"(p));
    return a;
}

// bf16 hi/lo split: returns packed (hi(a),hi(b)); lo_pack = (lo(a),lo(b))
__device__ __forceinline__ unsigned bfsplit_pack(float a, float b, unsigned& lo_pack) {
    __nv_bfloat16 ha = __float2bfloat16(a), hb = __float2bfloat16(b);
    __nv_bfloat16 la = __float2bfloat16(a - __bfloat162float(ha));
    __nv_bfloat16 lb = __float2bfloat16(b - __bfloat162float(hb));
    lo_pack = (unsigned)__bfloat16_as_ushort(la) |
              ((unsigned)__bfloat16_as_ushort(lb) << 16);
    return (unsigned)__bfloat16_as_ushort(ha) |
           ((unsigned)__bfloat16_as_ushort(hb) << 16);
}

// m16n8k16 bf16 mma, fp32 accumulate (baseline PTX, sm_80+)
__device__ __forceinline__ void mma16816(float d[4], const unsigned a[4],
                                         unsigned b0, unsigned b1) {
    asm volatile(
        "mma.sync.aligned.m16n8k16.row.col.f32.bf16.bf16.f32 "
        "{%0,%1,%2,%3}, {%4,%5,%6,%7}, {%8,%9}, {%0,%1,%2,%3};"
        : "+f"(d[0]), "+f"(d[1]), "+f"(d[2]), "+f"(d[3])
        : "r"(a[0]), "r"(a[1]), "r"(a[2]), "r"(a[3]), "r"(b0), "r"(b1));
}

#define LDMATRIX_X4(b0, b1, b2, b3, addr) \
    asm volatile("ldmatrix.sync.aligned.m8n8.x4.shared.b16 {%0,%1,%2,%3}, [%4];" \
                 : "=r"(b0), "=r"(b1), "=r"(b2), "=r"(b3) : "r"(addr))

// ---------------- no-op (launch-slot alignment) ----------------
__global__ void noop_kernel() {}

// ---------------- zero stats ----------------
__global__ void zero_stats_kernel() {
    int t = threadIdx.x;           // 512 threads
    if (t < 128)      { g_sum[1][t] = 0.0;       g_sqs[1][t] = 0.0; }
    else if (t < 256) { g_sum[2][t - 128] = 0.0; g_sqs[2][t - 128] = 0.0; }
    if (t < 9) g_mom[t] = 0.0;
}

// ---------------- farthest point sampling (1024 thr, 4 pts/thread; R14 exact) ---------
__global__ void fps_kernel(const float* __restrict__ xyz,
                           const int* __restrict__ initf,
                           float* __restrict__ newxyz) {
    __shared__ unsigned wkd[2][32], wki[2][32];

    const int b = blockIdx.x, tid = threadIdx.x;
    const int lane = tid & 31, w = tid >> 5;
    const float* xb = xyz + (size_t)b * NPTS * 3;

    unsigned long long px2[2], py2[2], pz2[2];
    float dist[4];
#pragma unroll
    for (int u = 0; u < 2; u++) {
        int p0 = tid + 1024 * (2 * u);
        int p1 = tid + 1024 * (2 * u + 1);
        px2[u] = f2pack(xb[3 * p0 + 0], xb[3 * p1 + 0]);
        py2[u] = f2pack(xb[3 * p0 + 1], xb[3 * p1 + 1]);
        pz2[u] = f2pack(xb[3 * p0 + 2], xb[3 * p1 + 2]);
        dist[2 * u] = 1e10f; dist[2 * u + 1] = 1e10f;
    }
    int f = initf[b];
    __syncthreads();

    for (int it = 0; it < NPT; it++) {
        float cx = xb[3 * f + 0], cy = xb[3 * f + 1], cz = xb[3 * f + 2];
        if (tid == 0) {
            float* o = newxyz + (size_t)(b * NPT + it) * 3;
            o[0] = cx; o[1] = cy; o[2] = cz;
        }
        unsigned long long ncx = f2pack(-cx, -cx);
        unsigned long long ncy = f2pack(-cy, -cy);
        unsigned long long ncz = f2pack(-cz, -cz);

#pragma unroll
        for (int u = 0; u < 2; u++) {
            unsigned long long dx, dy, dz, xx, yy, zz, ss, dd;
            ADD2(dx, px2[u], ncx);
            ADD2(dy, py2[u], ncy);
            ADD2(dz, pz2[u], ncz);
            MUL2(xx, dx, dx);
            MUL2(yy, dy, dy);
            MUL2(zz, dz, dz);
            ADD2(ss, xx, yy);
            ADD2(dd, ss, zz);
            float d0, d1;
            f2unpack(dd, d0, d1);
            dist[2 * u]     = fminf(dist[2 * u], d0);
            dist[2 * u + 1] = fminf(dist[2 * u + 1], d1);
        }
        float dmax = fmaxf(fmaxf(dist[0], dist[1]), fmaxf(dist[2], dist[3]));
        unsigned mw = __reduce_max_sync(0xFFFFFFFFu, __float_as_uint(dmax));
        unsigned ic[4];
#pragma unroll
        for (int j = 0; j < 4; j++)
            ic[j] = (__float_as_uint(dist[j]) == mw)
                      ? (unsigned)(tid + 1024 * j) : 0xFFFFFFFFu;
        unsigned widx = __reduce_min_sync(0xFFFFFFFFu,
                          umin(umin(ic[0], ic[1]), umin(ic[2], ic[3])));

        if (lane == 0) { wkd[it & 1][w] = mw; wki[it & 1][w] = widx; }
        __syncthreads();
        unsigned dl = wkd[it & 1][lane];
        unsigned il = wki[it & 1][lane];
        unsigned dm = __reduce_max_sync(0xFFFFFFFFu, dl);
        unsigned cand = (dl == dm) ? il : 0xFFFFFFFFu;
        f = (int)__reduce_min_sync(0xFFFFFFFFu, cand);
    }
}

// ---------------- kNN (top-33 smallest, drop rank 0) ----------------
__global__ void knn_kernel(const float* __restrict__ newxyz) {
    __shared__ unsigned long long sl[128][33];
    float* qx = (float*)&sl[0][0];
    float* qy = qx + NPT;
    float* qz = qy + NPT;

    const int tid = threadIdx.x, lane = tid & 31, w = tid >> 5;
    const int b = blockIdx.x >> 8;
    const int s = ((blockIdx.x & 255) << 2) | w;
    const float* nb = newxyz + (size_t)b * NPT * 3;

    for (int i = tid; i < NPT; i += 128) {
        qx[i] = nb[3 * i + 0];
        qy[i] = nb[3 * i + 1];
        qz[i] = nb[3 * i + 2];
    }
    __syncthreads();

    const float x = qx[s], y = qy[s], z = qz[s];

    unsigned long long r[32];
#pragma unroll
    for (int u = 0; u < 32; u++) {
        int j = lane + 32 * u;
        float dx = __fsub_rn(qx[j], x);
        float dy = __fsub_rn(qy[j], y);
        float dz = __fsub_rn(qz[j], z);
        float d = __fadd_rn(__fadd_rn(__fmul_rn(dx, dx), __fmul_rn(dy, dy)),
                            __fmul_rn(dz, dz));
        r[u] = ((unsigned long long)__float_as_uint(d) << 32) | (unsigned)j;
    }
    __syncthreads();

#pragma unroll
    for (int k = 2; k <= 32; k <<= 1) {
#pragma unroll
        for (int j = k >> 1; j > 0; j >>= 1) {
#pragma unroll
            for (int i = 0; i < 32; i++) {
                int ixj = i ^ j;
                if (ixj > i) {
                    bool up = ((i & k) == 0);
                    unsigned long long a = r[i], bb = r[ixj];
                    if ((a > bb) == up) { r[i] = bb; r[ixj] = a; }
                }
            }
        }
    }

#pragma unroll
    for (int u = 2; u < 32; u++) sl[tid][u] = r[u];

    unsigned ch = (unsigned)(r[0] >> 32), cl = (unsigned)r[0];
    unsigned nh = (unsigned)(r[1] >> 32), nl = (unsigned)r[1];
    int h = 2;
    int myidx = 0;
    for (int t = 0; t < 33; t++) {
        unsigned dm = __reduce_min_sync(0xFFFFFFFFu, ch);
        unsigned jc = (ch == dm) ? cl : 0xFFFFFFFFu;
        unsigned jm = __reduce_min_sync(0xFFFFFFFFu, jc);
        if (t && lane == t - 1) myidx = (int)jm;
        if (ch == dm && cl == jm) {
            ch = nh; cl = nl;
            if (h < 32) {
                unsigned long long nx = sl[tid][h];
                nh = (unsigned)(nx >> 32);
                nl = (unsigned)nx;
            } else {
                nh = 0xFFFFFFFFu;
                nl = 0xFFFFFFFFu;
            }
            h++;
        }
    }
    g_knn[(size_t)(b * NPT + s) * KNN + lane] = myidx;
}

// ---------------- grouping: gather z = xyz[knn] - center, 9 moments ----------------
__global__ void group_kernel(const float* __restrict__ xyz,
                             const float* __restrict__ newxyz) {
    __shared__ float wm[8][9];
    const int i = blockIdx.x * 256 + threadIdx.x;
    int2 jj = ((const int2*)g_knn)[i];
    int bs = i >> 4;
    int b = bs >> 10;
    const float* np = newxyz + (size_t)bs * 3;
    float nx = np[0], ny = np[1], nz = np[2];
    const float* p0 = xyz + (size_t)(b * NPTS + jj.x) * 3;
    const float* p1 = xyz + (size_t)(b * NPTS + jj.y) * 3;
    float x0 = p0[0] - nx, y0 = p0[1] - ny, z0 = p0[2] - nz;
    float x1 = p1[0] - nx, y1 = p1[1] - ny, z1 = p1[2] - nz;
    float4* z4 = (float4*)g_z;
    z4[2 * i]     = make_float4(x0, x1, y0, y1);
    z4[2 * i + 1] = make_float4(z0, z1, 0.f, 0.f);

    float m[9] = { x0 + x1, y0 + y1, z0 + z1,
                   x0 * x0 + x1 * x1, y0 * y0 + y1 * y1, z0 * z0 + z1 * z1,
                   x0 * y0 + x1 * y1, x0 * z0 + x1 * z1, y0 * z0 + y1 * z1 };
#pragma unroll
    for (int u = 0; u < 9; u++) {
        float v = m[u];
#pragma unroll
        for (int o = 16; o; o >>= 1) v += __shfl_xor_sync(0xFFFFFFFFu, v, o);
        if ((threadIdx.x & 31) == 0) wm[threadIdx.x >> 5][u] = v;
    }
    __syncthreads();
    if (threadIdx.x < 9) {
        float s = 0.f;
#pragma unroll
        for (int ww = 0; ww < 8; ww++) s += wm[ww][threadIdx.x];
        atomicAdd(&g_mom[threadIdx.x], (double)s);
    }
}

// ---------------- BN1 stats from moments ----------------
__global__ void finalize1_kernel(const float* __restrict__ W1,
                                 const float* __restrict__ b1,
                                 const float* __restrict__ g1,
                                 const float* __restrict__ be1) {
    int c = threadIdx.x;   // 64
    double w0 = W1[3 * c], w1 = W1[3 * c + 1], w2 = W1[3 * c + 2], b = b1[c];
    double Sx = g_mom[0], Sy = g_mom[1], Sz = g_mom[2];
    double Sxx = g_mom[3], Syy = g_mom[4], Szz = g_mom[5];
    double Sxy = g_mom[6], Sxz = g_mom[7], Syz = g_mom[8];
    double N = (double)POSN;
    double ws = w0 * Sx + w1 * Sy + w2 * Sz;
    double mean = (ws + N * b) / N;
    double ey2 = (w0 * w0 * Sxx + w1 * w1 * Syy + w2 * w2 * Szz
                + 2.0 * (w0 * w1 * Sxy + w0 * w2 * Sxz + w1 * w2 * Syz)
                + 2.0 * b * ws + N * b * b) / N;
    double var = ey2 - mean * mean;
    if (var < 0.0) var = 0.0;
    float sc = g1[c] * rsqrtf((float)var + 1e-5f);
    g_scale[0][c] = sc;
    g_shift[0][c] = be1[c] - (float)mean * sc;
}

// ---------------- layer 2: HMMA bf16-split GEMM, reg-prefetch pipelined ----------------
__global__ void __launch_bounds__(256, 2)
layer2_kernel(const float* __restrict__ W, const float* __restrict__ bias,
              const float* __restrict__ W1, const float* __restrict__ b1) {
    __shared__ __align__(16) unsigned short ah[64][72];
    __shared__ __align__(16) unsigned short al[64][72];
    __shared__ float4 sw1f[64];   // fused (sc*w0, sc*w1, sc*w2, sc*b + sh)

    const int tid = threadIdx.x;
    const int lane = tid & 31, w = tid >> 5;
    const int g = lane >> 2, t = lane & 3;
    const int ph = w >> 2, cq = w & 3;

    if (tid < 64) {
        float sc = g_scale[0][tid], sh = g_shift[0][tid];
        sw1f[tid] = make_float4(sc * W1[3 * tid], sc * W1[3 * tid + 1],
                                sc * W1[3 * tid + 2], fmaf(sc, b1[tid], sh));
    }

    unsigned Ah[4][4], Al[4][4];
    {
        const float* w0p = W + (cq * 16 + g) * 64;
        const float* w1p = W + (cq * 16 + g + 8) * 64;
#pragma unroll
        for (int kk = 0; kk < 4; kk++) {
            int c0 = kk * 16 + 2 * t;
            float2 p00 = *(const float2*)(w0p + c0);
            float2 p01 = *(const float2*)(w0p + c0 + 8);
            float2 p10 = *(const float2*)(w1p + c0);
            float2 p11 = *(const float2*)(w1p + c0 + 8);
            Ah[kk][0] = bfsplit_pack(p00.x, p00.y, Al[kk][0]);
            Ah[kk][1] = bfsplit_pack(p10.x, p10.y, Al[kk][1]);
            Ah[kk][2] = bfsplit_pack(p01.x, p01.y, Al[kk][2]);
            Ah[kk][3] = bfsplit_pack(p11.x, p11.y, Al[kk][3]);
        }
    }
    const float biasA = bias[cq * 16 + g];
    const float biasB = bias[cq * 16 + g + 8];

    const uint32_t ah_base = smem_u32(&ah[0][0]) + (uint32_t)(ph * 32 * 144);
    const uint32_t al_base = smem_u32(&al[0][0]) + (uint32_t)(ph * 32 * 144);
    const uint32_t laddr = (uint32_t)((lane & 7) * 144 + (lane >> 3) * 16);

    const int pl = tid >> 3, cb = tid & 7;
    __syncthreads();
    float4 wf[8];
#pragma unroll
    for (int i = 0; i < 8; i++) wf[i] = sw1f[8 * cb + i];

    const float4* z4 = (const float4*)g_z;
    float2* y2p = (float2*)g_y2;
    float sA = 0.f, s2A = 0.f, sB = 0.f, s2B = 0.f;

    int tile = blockIdx.x;
    float4 pxy, pzz;
    if (tile < NTILES) {
        pxy = z4[(size_t)(tile * 32 + pl) * 2];
        pzz = z4[(size_t)(tile * 32 + pl) * 2 + 1];
    }

    for (; tile < NTILES; tile += gridDim.x) {
        // ---- producer: y1 recompute + ReLU + bf16 split (from prefetched regs) ----
        {
            float4 xy = pxy, zz = pzz;
            unsigned h0[4], l0[4], h1[4], l1[4];
#pragma unroll
            for (int i = 0; i < 4; i++) {
                float4 wa = wf[2 * i], wb = wf[2 * i + 1];
                float va0 = fmaxf(fmaf(wa.x, xy.x, fmaf(wa.y, xy.z, fmaf(wa.z, zz.x, wa.w))), 0.f);
                float va1 = fmaxf(fmaf(wa.x, xy.y, fmaf(wa.y, xy.w, fmaf(wa.z, zz.y, wa.w))), 0.f);
                float vb0 = fmaxf(fmaf(wb.x, xy.x, fmaf(wb.y, xy.z, fmaf(wb.z, zz.x, wb.w))), 0.f);
                float vb1 = fmaxf(fmaf(wb.x, xy.y, fmaf(wb.y, xy.w, fmaf(wb.z, zz.y, wb.w))), 0.f);
                h0[i] = bfsplit_pack(va0, vb0, l0[i]);
                h1[i] = bfsplit_pack(va1, vb1, l1[i]);
            }
            *(uint4*)&ah[2 * pl][8 * cb]     = make_uint4(h0[0], h0[1], h0[2], h0[3]);
            *(uint4*)&ah[2 * pl + 1][8 * cb] = make_uint4(h1[0], h1[1], h1[2], h1[3]);
            *(uint4*)&al[2 * pl][8 * cb]     = make_uint4(l0[0], l0[1], l0[2], l0[3]);
            *(uint4*)&al[2 * pl + 1][8 * cb] = make_uint4(l1[0], l1[1], l1[2], l1[3]);
        }
        __syncthreads();

        // ---- prefetch next tile's z while MMA runs ----
        int nt = tile + gridDim.x;
        if (nt < NTILES) {
            pxy = z4[(size_t)(nt * 32 + pl) * 2];
            pzz = z4[(size_t)(nt * 32 + pl) * 2 + 1];
        }

        float d[4][4];
#pragma unroll
        for (int nf = 0; nf < 4; nf++)
#pragma unroll
            for (int j = 0; j < 4; j++) d[nf][j] = 0.f;

        auto do_pass = [&](const unsigned (&A)[4][4], uint32_t bbase) {
#pragma unroll
            for (int kh = 0; kh < 2; kh++) {
#pragma unroll
                for (int nf = 0; nf < 4; nf++) {
                    uint32_t addr = bbase + laddr + (uint32_t)(nf * 8 * 144 + kh * 64);
                    unsigned b0, b1, b2, b3;
                    LDMATRIX_X4(b0, b1, b2, b3, addr);
                    mma16816(d[nf], A[2 * kh],     b0, b1);
                    mma16816(d[nf], A[2 * kh + 1], b2, b3);
                }
            }
        };
        do_pass(Ah, ah_base);
        do_pass(Ah, al_base);
        do_pass(Al, ah_base);
        __syncthreads();

        // ---- epilogue ----
#pragma unroll
        for (int nf = 0; nf < 4; nf++) {
            size_t pair = (size_t)tile * 32 + ph * 16 + nf * 4 + t;
            float vA0 = d[nf][0] + biasA, vA1 = d[nf][1] + biasA;
            float vB0 = d[nf][2] + biasB, vB1 = d[nf][3] + biasB;
            y2p[pair * 64 + cq * 16 + g]     = make_float2(vA0, vA1);
            y2p[pair * 64 + cq * 16 + g + 8] = make_float2(vB0, vB1);
            sA += vA0 + vA1; s2A += vA0 * vA0 + vA1 * vA1;
            sB += vB0 + vB1; s2B += vB0 * vB0 + vB1 * vB1;
        }
    }

#pragma unroll
    for (int o = 1; o <= 2; o <<= 1) {
        sA += __shfl_xor_sync(0xFFFFFFFFu, sA, o);
        s2A += __shfl_xor_sync(0xFFFFFFFFu, s2A, o);
        sB += __shfl_xor_sync(0xFFFFFFFFu, sB, o);
        s2B += __shfl_xor_sync(0xFFFFFFFFu, s2B, o);
    }
    if (t == 0) {
        atomicAdd(&g_sum[1][cq * 16 + g],     (double)sA);
        atomicAdd(&g_sqs[1][cq * 16 + g],     (double)s2A);
        atomicAdd(&g_sum[1][cq * 16 + g + 8], (double)sB);
        atomicAdd(&g_sqs[1][cq * 16 + g + 8], (double)s2B);
    }
}

// ---------------- layer 3: HMMA bf16-split GEMM, reg-prefetch pipelined --------------
__global__ void __launch_bounds__(256, 2)
layer3_kernel(const float* __restrict__ W, const float* __restrict__ bias) {
    __shared__ __align__(16) unsigned short ah[32][72];
    __shared__ __align__(16) unsigned short al[32][72];
    __shared__ float ssc[64], ssh[64];

    const int tid = threadIdx.x;
    const int lane = tid & 31, w = tid >> 5;
    const int g = lane >> 2, t = lane & 3;

    if (tid < 64) { ssc[tid] = g_scale[1][tid]; ssh[tid] = g_shift[1][tid]; }

    unsigned Ah[4][4], Al[4][4];
    {
        const float* w0 = W + (w * 16 + g) * 64;
        const float* w1 = W + (w * 16 + g + 8) * 64;
#pragma unroll
        for (int kk = 0; kk < 4; kk++) {
            int c0 = kk * 16 + 2 * t;
            float2 p00 = *(const float2*)(w0 + c0);
            float2 p01 = *(const float2*)(w0 + c0 + 8);
            float2 p10 = *(const float2*)(w1 + c0);
            float2 p11 = *(const float2*)(w1 + c0 + 8);
            Ah[kk][0] = bfsplit_pack(p00.x, p00.y, Al[kk][0]);
            Ah[kk][1] = bfsplit_pack(p10.x, p10.y, Al[kk][1]);
            Ah[kk][2] = bfsplit_pack(p01.x, p01.y, Al[kk][2]);
            Ah[kk][3] = bfsplit_pack(p11.x, p11.y, Al[kk][3]);
        }
    }
    const float biasA = bias[w * 16 + g];
    const float biasB = bias[w * 16 + g + 8];

    const uint32_t ah_base = smem_u32(&ah[0][0]);
    const uint32_t al_base = smem_u32(&al[0][0]);
    const uint32_t laddr = (uint32_t)((lane & 7) * 144 + (lane >> 3) * 16);

    const int pl = tid >> 4, cb = tid & 15;
    __syncthreads();
    float sc0 = ssc[4 * cb], sh0 = ssh[4 * cb];
    float sc1 = ssc[4 * cb + 1], sh1 = ssh[4 * cb + 1];
    float sc2 = ssc[4 * cb + 2], sh2 = ssh[4 * cb + 2];
    float sc3 = ssc[4 * cb + 3], sh3 = ssh[4 * cb + 3];

    const float2* y2p = (const float2*)g_y2;
    float sA = 0.f, s2A = 0.f, sB = 0.f, s2B = 0.f;

    int tile = blockIdx.x;
    float4 pf0, pf1;
    if (tile < L3T) {
        const float4* src = (const float4*)(y2p + ((size_t)(tile * 16 + pl)) * 64 + 4 * cb);
        pf0 = src[0]; pf1 = src[1];
    }

    for (; tile < L3T; tile += gridDim.x) {
        // ---- producer: BN2+ReLU + bf16 split (from prefetched regs) ----
        {
            float4 f0 = pf0, f1 = pf1;
            float v00 = fmaxf(fmaf(f0.x, sc0, sh0), 0.f);
            float v10 = fmaxf(fmaf(f0.y, sc0, sh0), 0.f);
            float v01 = fmaxf(fmaf(f0.z, sc1, sh1), 0.f);
            float v11 = fmaxf(fmaf(f0.w, sc1, sh1), 0.f);
            float v02 = fmaxf(fmaf(f1.x, sc2, sh2), 0.f);
            float v12 = fmaxf(fmaf(f1.y, sc2, sh2), 0.f);
            float v03 = fmaxf(fmaf(f1.z, sc3, sh3), 0.f);
            float v13 = fmaxf(fmaf(f1.w, sc3, sh3), 0.f);
            uint2 h0, l0, h1, l1;
            h0.x = bfsplit_pack(v00, v01, l0.x);
            h0.y = bfsplit_pack(v02, v03, l0.y);
            h1.x = bfsplit_pack(v10, v11, l1.x);
            h1.y = bfsplit_pack(v12, v13, l1.y);
            *(uint2*)&ah[2 * pl][4 * cb]     = h0;
            *(uint2*)&ah[2 * pl + 1][4 * cb] = h1;
            *(uint2*)&al[2 * pl][4 * cb]     = l0;
            *(uint2*)&al[2 * pl + 1][4 * cb] = l1;
        }
        __syncthreads();

        // ---- prefetch next tile's y2 while MMA runs ----
        int nt = tile + gridDim.x;
        if (nt < L3T) {
            const float4* src = (const float4*)(y2p + ((size_t)(nt * 16 + pl)) * 64 + 4 * cb);
            pf0 = src[0]; pf1 = src[1];
        }

        float d[4][4];
#pragma unroll
        for (int nf = 0; nf < 4; nf++)
#pragma unroll
            for (int j = 0; j < 4; j++) d[nf][j] = 0.f;

        auto do_pass = [&](const unsigned (&A)[4][4], uint32_t bbase) {
#pragma unroll
            for (int kh = 0; kh < 2; kh++) {
#pragma unroll
                for (int nf = 0; nf < 4; nf++) {
                    uint32_t addr = bbase + laddr + (uint32_t)(nf * 8 * 144 + kh * 64);
                    unsigned b0, b1, b2, b3;
                    LDMATRIX_X4(b0, b1, b2, b3, addr);
                    mma16816(d[nf], A[2 * kh],     b0, b1);
                    mma16816(d[nf], A[2 * kh + 1], b2, b3);
                }
            }
        };
        do_pass(Ah, ah_base);
        do_pass(Ah, al_base);
        do_pass(Al, ah_base);
        __syncthreads();

        // ---- epilogue: bias, stats, k-max/min ----
        float mxA = -3.402823466e38f, mnA = 3.402823466e38f;
        float mxB = -3.402823466e38f, mnB = 3.402823466e38f;
#pragma unroll
        for (int nf = 0; nf < 4; nf++) {
            float vA0 = d[nf][0] + biasA, vA1 = d[nf][1] + biasA;
            float vB0 = d[nf][2] + biasB, vB1 = d[nf][3] + biasB;
            sA += vA0 + vA1; s2A += vA0 * vA0 + vA1 * vA1;
            sB += vB0 + vB1; s2B += vB0 * vB0 + vB1 * vB1;
            mxA = fmaxf(mxA, fmaxf(vA0, vA1)); mnA = fminf(mnA, fminf(vA0, vA1));
            mxB = fmaxf(mxB, fmaxf(vB0, vB1)); mnB = fminf(mnB, fminf(vB0, vB1));
        }
#pragma unroll
        for (int o = 1; o <= 2; o <<= 1) {
            mxA = fmaxf(mxA, __shfl_xor_sync(0xFFFFFFFFu, mxA, o));
            mnA = fminf(mnA, __shfl_xor_sync(0xFFFFFFFFu, mnA, o));
            mxB = fmaxf(mxB, __shfl_xor_sync(0xFFFFFFFFu, mxB, o));
            mnB = fminf(mnB, __shfl_xor_sync(0xFFFFFFFFu, mnB, o));
        }
        if (t == 0) {
            g_mm[(size_t)tile * 128 + w * 16 + g]     = make_float2(mxA, mnA);
            g_mm[(size_t)tile * 128 + w * 16 + g + 8] = make_float2(mxB, mnB);
        }
    }

#pragma unroll
    for (int o = 1; o <= 2; o <<= 1) {
        sA += __shfl_xor_sync(0xFFFFFFFFu, sA, o);
        s2A += __shfl_xor_sync(0xFFFFFFFFu, s2A, o);
        sB += __shfl_xor_sync(0xFFFFFFFFu, sB, o);
        s2B += __shfl_xor_sync(0xFFFFFFFFu, s2B, o);
    }
    if (t == 0) {
        atomicAdd(&g_sum[2][w * 16 + g],     (double)sA);
        atomicAdd(&g_sqs[2][w * 16 + g],     (double)s2A);
        atomicAdd(&g_sum[2][w * 16 + g + 8], (double)sB);
        atomicAdd(&g_sqs[2][w * 16 + g + 8], (double)s2B);
    }
}

// ---------------- BN finalize (layers 2,3) ----------------
__global__ void finalize_kernel(int l, const float* __restrict__ g,
                                const float* __restrict__ be, int C) {
    int c = threadIdx.x;
    if (c < C) {
        double n = (double)POSN;
        double m = g_sum[l][c] / n;
        double v = g_sqs[l][c] / n - m * m;
        if (v < 0.0) v = 0.0;
        float sc = g[c] * rsqrtf((float)v + 1e-5f);
        g_scale[l][c] = sc;
        g_shift[l][c] = be[c] - (float)m * sc;
    }
}

// ---------------- final: BN3+ReLU on max/min, transpose to [b,c,s] ----------------
__global__ void final_kernel(float* __restrict__ out) {
    __shared__ float tbuf[128 * 33];
    __shared__ float ssc[128], ssh[128];
    const int blk = blockIdx.x;
    const int b = blk >> 5, st = blk & 31;
    const int tid = threadIdx.x;
    if (tid < 128) { ssc[tid] = g_scale[2][tid]; ssh[tid] = g_shift[2][tid]; }
    __syncthreads();
#pragma unroll
    for (int rr = 0; rr < 16; rr++) {
        int e = tid + 256 * rr;
        int sl = e >> 7, cc = e & 127;
        float2 v = g_mm[((size_t)(b * NPT + st * 32 + sl)) * 128 + cc];
        float sc = ssc[cc], sh = ssh[cc];
        float val = (sc >= 0.f) ? fmaf(v.x, sc, sh) : fmaf(v.y, sc, sh);
        tbuf[cc * 33 + sl] = fmaxf(val, 0.f);
    }
    __syncthreads();
#pragma unroll
    for (int rr = 0; rr < 16; rr++) {
        int e = tid + 256 * rr;
        int c2 = e >> 5, s2 = e & 31;
        out[(size_t)(b * 128 + c2) * NPT + st * 32 + s2] = tbuf[c2 * 33 + s2];
    }
}

// ---------------- launch ----------------
extern "C" void kernel_launch(void* const* d_in, const int* in_sizes, int n_in,
                              void* d_out, int out_size) {
    const float* xyz   = (const float*)d_in[0];
    const int*   initf = (const int*)d_in[1];
    const float* W1 = (const float*)d_in[2];
    const float* b1 = (const float*)d_in[3];
    const float* g1 = (const float*)d_in[4];
    const float* be1 = (const float*)d_in[5];
    const float* W2 = (const float*)d_in[6];
    const float* b2 = (const float*)d_in[7];
    const float* g2 = (const float*)d_in[8];
    const float* be2 = (const float*)d_in[9];
    const float* W3 = (const float*)d_in[10];
    const float* b3 = (const float*)d_in[11];
    const float* g3 = (const float*)d_in[12];
    const float* be3 = (const float*)d_in[13];

    float* out = (float*)d_out;
    float* newxyz = out;                               // [16,1024,3]
    float* newpts = out + (size_t)BATCH * NPT * 3;     // [16,128,1024]

    fps_kernel<<<BATCH, 1024>>>(xyz, initf, newxyz);   // slot 1
    zero_stats_kernel<<<1, 512>>>();                   // slot 2
    noop_kernel<<<1, 32>>>();                          // slot 3
    knn_kernel<<<BATCH * 256, 128>>>(newxyz);          // slot 4 -> profiled
    group_kernel<<<NPAIR / 256, 256>>>(xyz, newxyz);
    finalize1_kernel<<<1, 64>>>(W1, b1, g1, be1);
    layer2_kernel<<<296, 256>>>(W2, b2, W1, b1);
    finalize_kernel<<<1, 128>>>(1, g2, be2, 64);
    layer3_kernel<<<296, 256>>>(W3, b3);
    finalize_kernel<<<1, 128>>>(2, g3, be3, 128);
    final_kernel<<<512, 256>>>(newpts);
}

// round 17
// speedup vs baseline: 1.5968x; 1.0001x over previous
#include <cuda_runtime.h>
#include <cuda_bf16.h>
#include <cstdint>

#define BATCH  16
#define NPTS   4096
#define NPT    1024
#define KNN    32
#define POSN   (BATCH*NPT*KNN)   // 524288 positions
#define NPAIR  (POSN/2)          // 262144 pairs
#define NTILES (POSN/64)         // 8192 layer2 tiles (64 positions)
#define L3T    (BATCH*NPT)       // 16384 layer3 tiles (one s-group = 32 positions)

// ---------------- scratch (device globals; no allocations allowed) ----------------
__device__ float  g_z[(size_t)POSN * 4];
__device__ float  g_y2[(size_t)POSN * 64];        // [NPAIR][64] float2 (pair-major)
__device__ float2 g_mm[(size_t)BATCH * NPT * 128];// per (b,s,c): (max_k, min_k) of pre-BN y3
__device__ double g_mom[9];
__device__ double g_sum[3][128];
__device__ double g_sqs[3][128];
__device__ float  g_scale[3][128];
__device__ float  g_shift[3][128];

// ---- f32x2 helpers ----
__device__ __forceinline__ unsigned long long f2pack(float a, float b) {
    unsigned long long v;
    asm("mov.b64 %0, {%1, %2};" : "=l"(v) : "f"(a), "f"(b));
    return v;
}
__device__ __forceinline__ void f2unpack(unsigned long long v, float& a, float& b) {
    asm("mov.b64 {%0, %1}, %2;" : "=f"(a), "=f"(b) : "l"(v));
}
#define ADD2(d, a, b) \
    asm("add.rn.f32x2 %0, %1, %2;" : "=l"(d) : "l"(a), "l"(b))
#define MUL2(d, a, b) \
    asm("mul.rn.f32x2 %0, %1, %2;" : "=l"(d) : "l"(a), "l"(b))

__device__ __forceinline__ uint32_t smem_u32(const void* p) {
    uint32_t a;
    asm("{ .reg .u64 t; cvta.to.shared.u64 t, %1; cvt.u32.u64 %0, t; }"
        : "=r"(a) : "l"(p));
    return a;
}

// bf16 hi/lo split: returns packed (hi(a),hi(b)); lo_pack = (lo(a),lo(b))
__device__ __forceinline__ unsigned bfsplit_pack(float a, float b, unsigned& lo_pack) {
    __nv_bfloat16 ha = __float2bfloat16(a), hb = __float2bfloat16(b);
    __nv_bfloat16 la = __float2bfloat16(a - __bfloat162float(ha));
    __nv_bfloat16 lb = __float2bfloat16(b - __bfloat162float(hb));
    lo_pack = (unsigned)__bfloat16_as_ushort(la) |
              ((unsigned)__bfloat16_as_ushort(lb) << 16);
    return (unsigned)__bfloat16_as_ushort(ha) |
           ((unsigned)__bfloat16_as_ushort(hb) << 16);
}

// m16n8k16 bf16 mma, fp32 accumulate (baseline PTX, sm_80+)
__device__ __forceinline__ void mma16816(float d[4], const unsigned a[4],
                                         unsigned b0, unsigned b1) {
    asm volatile(
        "mma.sync.aligned.m16n8k16.row.col.f32.bf16.bf16.f32 "
        "{%0,%1,%2,%3}, {%4,%5,%6,%7}, {%8,%9}, {%0,%1,%2,%3};"
        : "+f"(d[0]), "+f"(d[1]), "+f"(d[2]), "+f"(d[3])
        : "r"(a[0]), "r"(a[1]), "r"(a[2]), "r"(a[3]), "r"(b0), "r"(b1));
}

#define LDMATRIX_X4(b0, b1, b2, b3, addr) \
    asm volatile("ldmatrix.sync.aligned.m8n8.x4.shared.b16 {%0,%1,%2,%3}, [%4];" \
                 : "=r"(b0), "=r"(b1), "=r"(b2), "=r"(b3) : "r"(addr))

// ---------------- farthest point sampling (1024 thr, 4 pts/thread) ----------------
// Block 0 additionally zeroes the global stats (replaces zero_stats_kernel).
__global__ void fps_kernel(const float* __restrict__ xyz,
                           const int* __restrict__ initf,
                           float* __restrict__ newxyz) {
    __shared__ unsigned wkd[2][32], wki[2][32];

    const int b = blockIdx.x, tid = threadIdx.x;
    const int lane = tid & 31, w = tid >> 5;
    const float* xb = xyz + (size_t)b * NPTS * 3;

    if (b == 0) {
        if (tid < 128)      { g_sum[1][tid] = 0.0;       g_sqs[1][tid] = 0.0; }
        else if (tid < 256) { g_sum[2][tid - 128] = 0.0; g_sqs[2][tid - 128] = 0.0; }
        if (tid < 9) g_mom[tid] = 0.0;
    }

    unsigned long long px2[2], py2[2], pz2[2];
    float dist[4];
#pragma unroll
    for (int u = 0; u < 2; u++) {
        int p0 = tid + 1024 * (2 * u);
        int p1 = tid + 1024 * (2 * u + 1);
        px2[u] = f2pack(xb[3 * p0 + 0], xb[3 * p1 + 0]);
        py2[u] = f2pack(xb[3 * p0 + 1], xb[3 * p1 + 1]);
        pz2[u] = f2pack(xb[3 * p0 + 2], xb[3 * p1 + 2]);
        dist[2 * u] = 1e10f; dist[2 * u + 1] = 1e10f;
    }
    int f = initf[b];
    __syncthreads();

    for (int it = 0; it < NPT; it++) {
        float cx = xb[3 * f + 0], cy = xb[3 * f + 1], cz = xb[3 * f + 2];
        if (tid == 0) {
            float* o = newxyz + (size_t)(b * NPT + it) * 3;
            o[0] = cx; o[1] = cy; o[2] = cz;
        }
        unsigned long long ncx = f2pack(-cx, -cx);
        unsigned long long ncy = f2pack(-cy, -cy);
        unsigned long long ncz = f2pack(-cz, -cz);

#pragma unroll
        for (int u = 0; u < 2; u++) {
            unsigned long long dx, dy, dz, xx, yy, zz, ss, dd;
            ADD2(dx, px2[u], ncx);
            ADD2(dy, py2[u], ncy);
            ADD2(dz, pz2[u], ncz);
            MUL2(xx, dx, dx);
            MUL2(yy, dy, dy);
            MUL2(zz, dz, dz);
            ADD2(ss, xx, yy);
            ADD2(dd, ss, zz);
            float d0, d1;
            f2unpack(dd, d0, d1);
            dist[2 * u]     = fminf(dist[2 * u], d0);
            dist[2 * u + 1] = fminf(dist[2 * u + 1], d1);
        }
        float dmax = fmaxf(fmaxf(dist[0], dist[1]), fmaxf(dist[2], dist[3]));
        unsigned mw = __reduce_max_sync(0xFFFFFFFFu, __float_as_uint(dmax));
        unsigned ic[4];
#pragma unroll
        for (int j = 0; j < 4; j++)
            ic[j] = (__float_as_uint(dist[j]) == mw)
                      ? (unsigned)(tid + 1024 * j) : 0xFFFFFFFFu;
        unsigned widx = __reduce_min_sync(0xFFFFFFFFu,
                          umin(umin(ic[0], ic[1]), umin(ic[2], ic[3])));

        if (lane == 0) { wkd[it & 1][w] = mw; wki[it & 1][w] = widx; }
        __syncthreads();
        unsigned dl = wkd[it & 1][lane];
        unsigned il = wki[it & 1][lane];
        unsigned dm = __reduce_max_sync(0xFFFFFFFFu, dl);
        unsigned cand = (dl == dm) ? il : 0xFFFFFFFFu;
        f = (int)__reduce_min_sync(0xFFFFFFFFu, cand);
    }
}

// ---------------- kNN + grouping fused ----------------
// Warp per query: top-33 via register bitonic + REDUX merge (exact stable
// order), then each lane gathers its neighbor, computes z = xyz[j] - center,
// stores pair-packed g_z, and contributes the 9 moment sums.
__global__ void knn_kernel(const float* __restrict__ newxyz,
                           const float* __restrict__ xyz) {
    __shared__ unsigned long long sl[128][33];
    __shared__ float wm[4][9];
    float* qx = (float*)&sl[0][0];
    float* qy = qx + NPT;
    float* qz = qy + NPT;

    const int tid = threadIdx.x, lane = tid & 31, w = tid >> 5;
    const int b = blockIdx.x >> 8;
    const int s = ((blockIdx.x & 255) << 2) | w;
    const float* nb = newxyz + (size_t)b * NPT * 3;

    for (int i = tid; i < NPT; i += 128) {
        qx[i] = nb[3 * i + 0];
        qy[i] = nb[3 * i + 1];
        qz[i] = nb[3 * i + 2];
    }
    __syncthreads();

    const float x = qx[s], y = qy[s], z = qz[s];

    unsigned long long r[32];
#pragma unroll
    for (int u = 0; u < 32; u++) {
        int j = lane + 32 * u;
        float dx = __fsub_rn(qx[j], x);
        float dy = __fsub_rn(qy[j], y);
        float dz = __fsub_rn(qz[j], z);
        float d = __fadd_rn(__fadd_rn(__fmul_rn(dx, dx), __fmul_rn(dy, dy)),
                            __fmul_rn(dz, dz));
        r[u] = ((unsigned long long)__float_as_uint(d) << 32) | (unsigned)j;
    }
    __syncthreads();   // coords consumed; sl may be overwritten

#pragma unroll
    for (int k = 2; k <= 32; k <<= 1) {
#pragma unroll
        for (int j = k >> 1; j > 0; j >>= 1) {
#pragma unroll
            for (int i = 0; i < 32; i++) {
                int ixj = i ^ j;
                if (ixj > i) {
                    bool up = ((i & k) == 0);
                    unsigned long long a = r[i], bb = r[ixj];
                    if ((a > bb) == up) { r[i] = bb; r[ixj] = a; }
                }
            }
        }
    }

#pragma unroll
    for (int u = 2; u < 32; u++) sl[tid][u] = r[u];

    unsigned ch = (unsigned)(r[0] >> 32), cl = (unsigned)r[0];
    unsigned nh = (unsigned)(r[1] >> 32), nl = (unsigned)r[1];
    int h = 2;
    int myidx = 0;
    for (int t = 0; t < 33; t++) {
        unsigned dm = __reduce_min_sync(0xFFFFFFFFu, ch);
        unsigned jc = (ch == dm) ? cl : 0xFFFFFFFFu;
        unsigned jm = __reduce_min_sync(0xFFFFFFFFu, jc);
        if (t && lane == t - 1) myidx = (int)jm;
        if (ch == dm && cl == jm) {
            ch = nh; cl = nl;
            if (h < 32) {
                unsigned long long nx = sl[tid][h];
                nh = (unsigned)(nx >> 32);
                nl = (unsigned)nx;
            } else {
                nh = 0xFFFFFFFFu;
                nl = 0xFFFFFFFFu;
            }
            h++;
        }
    }

    // ---- fused grouping: z = xyz[b][myidx] - (x,y,z) ----
    const float* xp = xyz + ((size_t)b * NPTS + myidx) * 3;
    float zx = xp[0] - x, zy = xp[1] - y, zz = xp[2] - z;

    float zxo = __shfl_down_sync(0xFFFFFFFFu, zx, 1);
    float zyo = __shfl_down_sync(0xFFFFFFFFu, zy, 1);
    float zzo = __shfl_down_sync(0xFFFFFFFFu, zz, 1);
    if (!(lane & 1)) {
        size_t i = (size_t)(b * NPT + s) * 16 + (lane >> 1);
        float4* z4 = (float4*)g_z;
        z4[2 * i]     = make_float4(zx, zxo, zy, zyo);
        z4[2 * i + 1] = make_float4(zz, zzo, 0.f, 0.f);
    }

    float m[9] = { zx, zy, zz, zx * zx, zy * zy, zz * zz,
                   zx * zy, zx * zz, zy * zz };
#pragma unroll
    for (int u = 0; u < 9; u++) {
        float v = m[u];
#pragma unroll
        for (int o = 16; o; o >>= 1) v += __shfl_xor_sync(0xFFFFFFFFu, v, o);
        if (lane == 0) wm[w][u] = v;
    }
    __syncthreads();
    if (tid < 9) {
        float sm = wm[0][tid] + wm[1][tid] + wm[2][tid] + wm[3][tid];
        atomicAdd(&g_mom[tid], (double)sm);
    }
}

// ---------------- BN1 stats from moments ----------------
__global__ void finalize1_kernel(const float* __restrict__ W1,
                                 const float* __restrict__ b1,
                                 const float* __restrict__ g1,
                                 const float* __restrict__ be1) {
    int c = threadIdx.x;   // 64
    double w0 = W1[3 * c], w1 = W1[3 * c + 1], w2 = W1[3 * c + 2], b = b1[c];
    double Sx = g_mom[0], Sy = g_mom[1], Sz = g_mom[2];
    double Sxx = g_mom[3], Syy = g_mom[4], Szz = g_mom[5];
    double Sxy = g_mom[6], Sxz = g_mom[7], Syz = g_mom[8];
    double N = (double)POSN;
    double ws = w0 * Sx + w1 * Sy + w2 * Sz;
    double mean = (ws + N * b) / N;
    double ey2 = (w0 * w0 * Sxx + w1 * w1 * Syy + w2 * w2 * Szz
                + 2.0 * (w0 * w1 * Sxy + w0 * w2 * Sxz + w1 * w2 * Syz)
                + 2.0 * b * ws + N * b * b) / N;
    double var = ey2 - mean * mean;
    if (var < 0.0) var = 0.0;
    float sc = g1[c] * rsqrtf((float)var + 1e-5f);
    g_scale[0][c] = sc;
    g_shift[0][c] = be1[c] - (float)mean * sc;
}

// ---------------- layer 2: HMMA bf16-split GEMM, reg-prefetch pipelined ----------------
__global__ void __launch_bounds__(256, 2)
layer2_kernel(const float* __restrict__ W, const float* __restrict__ bias,
              const float* __restrict__ W1, const float* __restrict__ b1) {
    __shared__ __align__(16) unsigned short ah[64][72];
    __shared__ __align__(16) unsigned short al[64][72];
    __shared__ float4 sw1f[64];   // fused (sc*w0, sc*w1, sc*w2, sc*b + sh)

    const int tid = threadIdx.x;
    const int lane = tid & 31, w = tid >> 5;
    const int g = lane >> 2, t = lane & 3;
    const int ph = w >> 2, cq = w & 3;

    if (tid < 64) {
        float sc = g_scale[0][tid], sh = g_shift[0][tid];
        sw1f[tid] = make_float4(sc * W1[3 * tid], sc * W1[3 * tid + 1],
                                sc * W1[3 * tid + 2], fmaf(sc, b1[tid], sh));
    }

    unsigned Ah[4][4], Al[4][4];
    {
        const float* w0p = W + (cq * 16 + g) * 64;
        const float* w1p = W + (cq * 16 + g + 8) * 64;
#pragma unroll
        for (int kk = 0; kk < 4; kk++) {
            int c0 = kk * 16 + 2 * t;
            float2 p00 = *(const float2*)(w0p + c0);
            float2 p01 = *(const float2*)(w0p + c0 + 8);
            float2 p10 = *(const float2*)(w1p + c0);
            float2 p11 = *(const float2*)(w1p + c0 + 8);
            Ah[kk][0] = bfsplit_pack(p00.x, p00.y, Al[kk][0]);
            Ah[kk][1] = bfsplit_pack(p10.x, p10.y, Al[kk][1]);
            Ah[kk][2] = bfsplit_pack(p01.x, p01.y, Al[kk][2]);
            Ah[kk][3] = bfsplit_pack(p11.x, p11.y, Al[kk][3]);
        }
    }
    const float biasA = bias[cq * 16 + g];
    const float biasB = bias[cq * 16 + g + 8];

    const uint32_t ah_base = smem_u32(&ah[0][0]) + (uint32_t)(ph * 32 * 144);
    const uint32_t al_base = smem_u32(&al[0][0]) + (uint32_t)(ph * 32 * 144);
    const uint32_t laddr = (uint32_t)((lane & 7) * 144 + (lane >> 3) * 16);

    const int pl = tid >> 3, cb = tid & 7;
    __syncthreads();
    float4 wf[8];
#pragma unroll
    for (int i = 0; i < 8; i++) wf[i] = sw1f[8 * cb + i];

    const float4* z4 = (const float4*)g_z;
    float2* y2p = (float2*)g_y2;
    float sA = 0.f, s2A = 0.f, sB = 0.f, s2B = 0.f;

    int tile = blockIdx.x;
    float4 pxy, pzz;
    if (tile < NTILES) {
        pxy = z4[(size_t)(tile * 32 + pl) * 2];
        pzz = z4[(size_t)(tile * 32 + pl) * 2 + 1];
    }

    for (; tile < NTILES; tile += gridDim.x) {
        {
            float4 xy = pxy, zz = pzz;
            unsigned h0[4], l0[4], h1[4], l1[4];
#pragma unroll
            for (int i = 0; i < 4; i++) {
                float4 wa = wf[2 * i], wb = wf[2 * i + 1];
                float va0 = fmaxf(fmaf(wa.x, xy.x, fmaf(wa.y, xy.z, fmaf(wa.z, zz.x, wa.w))), 0.f);
                float va1 = fmaxf(fmaf(wa.x, xy.y, fmaf(wa.y, xy.w, fmaf(wa.z, zz.y, wa.w))), 0.f);
                float vb0 = fmaxf(fmaf(wb.x, xy.x, fmaf(wb.y, xy.z, fmaf(wb.z, zz.x, wb.w))), 0.f);
                float vb1 = fmaxf(fmaf(wb.x, xy.y, fmaf(wb.y, xy.w, fmaf(wb.z, zz.y, wb.w))), 0.f);
                h0[i] = bfsplit_pack(va0, vb0, l0[i]);
                h1[i] = bfsplit_pack(va1, vb1, l1[i]);
            }
            *(uint4*)&ah[2 * pl][8 * cb]     = make_uint4(h0[0], h0[1], h0[2], h0[3]);
            *(uint4*)&ah[2 * pl + 1][8 * cb] = make_uint4(h1[0], h1[1], h1[2], h1[3]);
            *(uint4*)&al[2 * pl][8 * cb]     = make_uint4(l0[0], l0[1], l0[2], l0[3]);
            *(uint4*)&al[2 * pl + 1][8 * cb] = make_uint4(l1[0], l1[1], l1[2], l1[3]);
        }
        __syncthreads();

        int nt = tile + gridDim.x;
        if (nt < NTILES) {
            pxy = z4[(size_t)(nt * 32 + pl) * 2];
            pzz = z4[(size_t)(nt * 32 + pl) * 2 + 1];
        }

        float d[4][4];
#pragma unroll
        for (int nf = 0; nf < 4; nf++)
#pragma unroll
            for (int j = 0; j < 4; j++) d[nf][j] = 0.f;

        auto do_pass = [&](const unsigned (&A)[4][4], uint32_t bbase) {
#pragma unroll
            for (int kh = 0; kh < 2; kh++) {
#pragma unroll
                for (int nf = 0; nf < 4; nf++) {
                    uint32_t addr = bbase + laddr + (uint32_t)(nf * 8 * 144 + kh * 64);
                    unsigned b0, b1, b2, b3;
                    LDMATRIX_X4(b0, b1, b2, b3, addr);
                    mma16816(d[nf], A[2 * kh],     b0, b1);
                    mma16816(d[nf], A[2 * kh + 1], b2, b3);
                }
            }
        };
        do_pass(Ah, ah_base);
        do_pass(Ah, al_base);
        do_pass(Al, ah_base);
        __syncthreads();

#pragma unroll
        for (int nf = 0; nf < 4; nf++) {
            size_t pair = (size_t)tile * 32 + ph * 16 + nf * 4 + t;
            float vA0 = d[nf][0] + biasA, vA1 = d[nf][1] + biasA;
            float vB0 = d[nf][2] + biasB, vB1 = d[nf][3] + biasB;
            y2p[pair * 64 + cq * 16 + g]     = make_float2(vA0, vA1);
            y2p[pair * 64 + cq * 16 + g + 8] = make_float2(vB0, vB1);
            sA += vA0 + vA1; s2A += vA0 * vA0 + vA1 * vA1;
            sB += vB0 + vB1; s2B += vB0 * vB0 + vB1 * vB1;
        }
    }

#pragma unroll
    for (int o = 1; o <= 2; o <<= 1) {
        sA += __shfl_xor_sync(0xFFFFFFFFu, sA, o);
        s2A += __shfl_xor_sync(0xFFFFFFFFu, s2A, o);
        sB += __shfl_xor_sync(0xFFFFFFFFu, sB, o);
        s2B += __shfl_xor_sync(0xFFFFFFFFu, s2B, o);
    }
    if (t == 0) {
        atomicAdd(&g_sum[1][cq * 16 + g],     (double)sA);
        atomicAdd(&g_sqs[1][cq * 16 + g],     (double)s2A);
        atomicAdd(&g_sum[1][cq * 16 + g + 8], (double)sB);
        atomicAdd(&g_sqs[1][cq * 16 + g + 8], (double)s2B);
    }
}

// ---------------- layer 3: HMMA bf16-split GEMM, reg-prefetch, 3 blocks/SM -----------
__global__ void __launch_bounds__(256, 3)
layer3_kernel(const float* __restrict__ W, const float* __restrict__ bias) {
    __shared__ __align__(16) unsigned short ah[32][72];
    __shared__ __align__(16) unsigned short al[32][72];
    __shared__ float ssc[64], ssh[64];

    const int tid = threadIdx.x;
    const int lane = tid & 31, w = tid >> 5;
    const int g = lane >> 2, t = lane & 3;

    if (tid < 64) { ssc[tid] = g_scale[1][tid]; ssh[tid] = g_shift[1][tid]; }

    unsigned Ah[4][4], Al[4][4];
    {
        const float* w0 = W + (w * 16 + g) * 64;
        const float* w1 = W + (w * 16 + g + 8) * 64;
#pragma unroll
        for (int kk = 0; kk < 4; kk++) {
            int c0 = kk * 16 + 2 * t;
            float2 p00 = *(const float2*)(w0 + c0);
            float2 p01 = *(const float2*)(w0 + c0 + 8);
            float2 p10 = *(const float2*)(w1 + c0);
            float2 p11 = *(const float2*)(w1 + c0 + 8);
            Ah[kk][0] = bfsplit_pack(p00.x, p00.y, Al[kk][0]);
            Ah[kk][1] = bfsplit_pack(p10.x, p10.y, Al[kk][1]);
            Ah[kk][2] = bfsplit_pack(p01.x, p01.y, Al[kk][2]);
            Ah[kk][3] = bfsplit_pack(p11.x, p11.y, Al[kk][3]);
        }
    }
    const float biasA = bias[w * 16 + g];
    const float biasB = bias[w * 16 + g + 8];

    const uint32_t ah_base = smem_u32(&ah[0][0]);
    const uint32_t al_base = smem_u32(&al[0][0]);
    const uint32_t laddr = (uint32_t)((lane & 7) * 144 + (lane >> 3) * 16);

    const int pl = tid >> 4, cb = tid & 15;
    __syncthreads();
    float sc0 = ssc[4 * cb], sh0 = ssh[4 * cb];
    float sc1 = ssc[4 * cb + 1], sh1 = ssh[4 * cb + 1];
    float sc2 = ssc[4 * cb + 2], sh2 = ssh[4 * cb + 2];
    float sc3 = ssc[4 * cb + 3], sh3 = ssh[4 * cb + 3];

    const float2* y2p = (const float2*)g_y2;
    float sA = 0.f, s2A = 0.f, sB = 0.f, s2B = 0.f;

    int tile = blockIdx.x;
    float4 pf0, pf1;
    if (tile < L3T) {
        const float4* src = (const float4*)(y2p + ((size_t)(tile * 16 + pl)) * 64 + 4 * cb);
        pf0 = src[0]; pf1 = src[1];
    }

    for (; tile < L3T; tile += gridDim.x) {
        {
            float4 f0 = pf0, f1 = pf1;
            float v00 = fmaxf(fmaf(f0.x, sc0, sh0), 0.f);
            float v10 = fmaxf(fmaf(f0.y, sc0, sh0), 0.f);
            float v01 = fmaxf(fmaf(f0.z, sc1, sh1), 0.f);
            float v11 = fmaxf(fmaf(f0.w, sc1, sh1), 0.f);
            float v02 = fmaxf(fmaf(f1.x, sc2, sh2), 0.f);
            float v12 = fmaxf(fmaf(f1.y, sc2, sh2), 0.f);
            float v03 = fmaxf(fmaf(f1.z, sc3, sh3), 0.f);
            float v13 = fmaxf(fmaf(f1.w, sc3, sh3), 0.f);
            uint2 h0, l0, h1, l1;
            h0.x = bfsplit_pack(v00, v01, l0.x);
            h0.y = bfsplit_pack(v02, v03, l0.y);
            h1.x = bfsplit_pack(v10, v11, l1.x);
            h1.y = bfsplit_pack(v12, v13, l1.y);
            *(uint2*)&ah[2 * pl][4 * cb]     = h0;
            *(uint2*)&ah[2 * pl + 1][4 * cb] = h1;
            *(uint2*)&al[2 * pl][4 * cb]     = l0;
            *(uint2*)&al[2 * pl + 1][4 * cb] = l1;
        }
        __syncthreads();

        int nt = tile + gridDim.x;
        if (nt < L3T) {
            const float4* src = (const float4*)(y2p + ((size_t)(nt * 16 + pl)) * 64 + 4 * cb);
            pf0 = src[0]; pf1 = src[1];
        }

        float d[4][4];
#pragma unroll
        for (int nf = 0; nf < 4; nf++)
#pragma unroll
            for (int j = 0; j < 4; j++) d[nf][j] = 0.f;

        auto do_pass = [&](const unsigned (&A)[4][4], uint32_t bbase) {
#pragma unroll
            for (int kh = 0; kh < 2; kh++) {
#pragma unroll
                for (int nf = 0; nf < 4; nf++) {
                    uint32_t addr = bbase + laddr + (uint32_t)(nf * 8 * 144 + kh * 64);
                    unsigned b0, b1, b2, b3;
                    LDMATRIX_X4(b0, b1, b2, b3, addr);
                    mma16816(d[nf], A[2 * kh],     b0, b1);
                    mma16816(d[nf], A[2 * kh + 1], b2, b3);
                }
            }
        };
        do_pass(Ah, ah_base);
        do_pass(Ah, al_base);
        do_pass(Al, ah_base);
        __syncthreads();

        float mxA = -3.402823466e38f, mnA = 3.402823466e38f;
        float mxB = -3.402823466e38f, mnB = 3.402823466e38f;
#pragma unroll
        for (int nf = 0; nf < 4; nf++) {
            float vA0 = d[nf][0] + biasA, vA1 = d[nf][1] + biasA;
            float vB0 = d[nf][2] + biasB, vB1 = d[nf][3] + biasB;
            sA += vA0 + vA1; s2A += vA0 * vA0 + vA1 * vA1;
            sB += vB0 + vB1; s2B += vB0 * vB0 + vB1 * vB1;
            mxA = fmaxf(mxA, fmaxf(vA0, vA1)); mnA = fminf(mnA, fminf(vA0, vA1));
            mxB = fmaxf(mxB, fmaxf(vB0, vB1)); mnB = fminf(mnB, fminf(vB0, vB1));
        }
#pragma unroll
        for (int o = 1; o <= 2; o <<= 1) {
            mxA = fmaxf(mxA, __shfl_xor_sync(0xFFFFFFFFu, mxA, o));
            mnA = fminf(mnA, __shfl_xor_sync(0xFFFFFFFFu, mnA, o));
            mxB = fmaxf(mxB, __shfl_xor_sync(0xFFFFFFFFu, mxB, o));
            mnB = fminf(mnB, __shfl_xor_sync(0xFFFFFFFFu, mnB, o));
        }
        if (t == 0) {
            g_mm[(size_t)tile * 128 + w * 16 + g]     = make_float2(mxA, mnA);
            g_mm[(size_t)tile * 128 + w * 16 + g + 8] = make_float2(mxB, mnB);
        }
    }

#pragma unroll
    for (int o = 1; o <= 2; o <<= 1) {
        sA += __shfl_xor_sync(0xFFFFFFFFu, sA, o);
        s2A += __shfl_xor_sync(0xFFFFFFFFu, s2A, o);
        sB += __shfl_xor_sync(0xFFFFFFFFu, sB, o);
        s2B += __shfl_xor_sync(0xFFFFFFFFu, s2B, o);
    }
    if (t == 0) {
        atomicAdd(&g_sum[2][w * 16 + g],     (double)sA);
        atomicAdd(&g_sqs[2][w * 16 + g],     (double)s2A);
        atomicAdd(&g_sum[2][w * 16 + g + 8], (double)sB);
        atomicAdd(&g_sqs[2][w * 16 + g + 8], (double)s2B);
    }
}

// ---------------- BN finalize (layers 2,3) ----------------
__global__ void finalize_kernel(int l, const float* __restrict__ g,
                                const float* __restrict__ be, int C) {
    int c = threadIdx.x;
    if (c < C) {
        double n = (double)POSN;
        double m = g_sum[l][c] / n;
        double v = g_sqs[l][c] / n - m * m;
        if (v < 0.0) v = 0.0;
        float sc = g[c] * rsqrtf((float)v + 1e-5f);
        g_scale[l][c] = sc;
        g_shift[l][c] = be[c] - (float)m * sc;
    }
}

// ---------------- final: BN3+ReLU on max/min, transpose to [b,c,s] ----------------
__global__ void final_kernel(float* __restrict__ out) {
    __shared__ float tbuf[128 * 33];
    __shared__ float ssc[128], ssh[128];
    const int blk = blockIdx.x;
    const int b = blk >> 5, st = blk & 31;
    const int tid = threadIdx.x;
    if (tid < 128) { ssc[tid] = g_scale[2][tid]; ssh[tid] = g_shift[2][tid]; }
    __syncthreads();
#pragma unroll
    for (int rr = 0; rr < 16; rr++) {
        int e = tid + 256 * rr;
        int sl = e >> 7, cc = e & 127;
        float2 v = g_mm[((size_t)(b * NPT + st * 32 + sl)) * 128 + cc];
        float sc = ssc[cc], sh = ssh[cc];
        float val = (sc >= 0.f) ? fmaf(v.x, sc, sh) : fmaf(v.y, sc, sh);
        tbuf[cc * 33 + sl] = fmaxf(val, 0.f);
    }
    __syncthreads();
#pragma unroll
    for (int rr = 0; rr < 16; rr++) {
        int e = tid + 256 * rr;
        int c2 = e >> 5, s2 = e & 31;
        out[(size_t)(b * 128 + c2) * NPT + st * 32 + s2] = tbuf[c2 * 33 + s2];
    }
}

// ---------------- launch ----------------
extern "C" void kernel_launch(void* const* d_in, const int* in_sizes, int n_in,
                              void* d_out, int out_size) {
    const float* xyz   = (const float*)d_in[0];
    const int*   initf = (const int*)d_in[1];
    const float* W1 = (const float*)d_in[2];
    const float* b1 = (const float*)d_in[3];
    const float* g1 = (const float*)d_in[4];
    const float* be1 = (const float*)d_in[5];
    const float* W2 = (const float*)d_in[6];
    const float* b2 = (const float*)d_in[7];
    const float* g2 = (const float*)d_in[8];
    const float* be2 = (const float*)d_in[9];
    const float* W3 = (const float*)d_in[10];
    const float* b3 = (const float*)d_in[11];
    const float* g3 = (const float*)d_in[12];
    const float* be3 = (const float*)d_in[13];

    float* out = (float*)d_out;
    float* newxyz = out;                               // [16,1024,3]
    float* newpts = out + (size_t)BATCH * NPT * 3;     // [16,128,1024]

    fps_kernel<<<BATCH, 1024>>>(xyz, initf, newxyz);   // slot 1 (includes stat zeroing)
    knn_kernel<<<BATCH * 256, 128>>>(newxyz, xyz);     // slot 2 (includes grouping)
    finalize1_kernel<<<1, 64>>>(W1, b1, g1, be1);      // slot 3
    layer2_kernel<<<296, 256>>>(W2, b2, W1, b1);       // slot 4 -> profiled
    finalize_kernel<<<1, 128>>>(1, g2, be2, 64);
    layer3_kernel<<<444, 256>>>(W3, b3);
    finalize_kernel<<<1, 128>>>(2, g3, be3, 128);
    final_kernel<<<512, 256>>>(newpts);
}